// round 1
// baseline (speedup 1.0000x reference)
#include <cuda_runtime.h>
#include <cuda_bf16.h>

#define BB 4
#define NN 8192
#define MM 2048
#define KK 8
#define F1C 256
#define F2C 256
#define C0 259      // F2 + 3
#define H0 128
#define H1 128
#define H2 256
#define C2IN 512
#define C2OUT 256

// scratch (allocation-free rule: __device__ globals)
__device__ int   g_idx[BB * NN * KK];                    // 1 MB
__device__ float g_mid[(size_t)BB * H2 * NN];            // 32 MB

// ---------------------------------------------------------------------------
// KNN: for each pos1 point, top-8 nearest pos2 points.
// One thread per query point; pos2 (+norm) cached in smem as float4.
// ---------------------------------------------------------------------------
__global__ __launch_bounds__(256) void knn_kernel(const float* __restrict__ pos1,
                                                  const float* __restrict__ pos2) {
    __shared__ float4 sp[MM];                            // 32 KB
    const int b = blockIdx.y;
    const float* p2 = pos2 + (size_t)b * 3 * MM;
    for (int m = threadIdx.x; m < MM; m += blockDim.x) {
        float x = p2[m], y = p2[MM + m], z = p2[2 * MM + m];
        sp[m] = make_float4(x, y, z, x * x + y * y + z * z);
    }
    __syncthreads();

    const int n = blockIdx.x * blockDim.x + threadIdx.x;
    const float* p1 = pos1 + (size_t)b * 3 * NN;
    const float px = p1[n], py = p1[NN + n], pz = p1[2 * NN + n];
    const float n1 = px * px + py * py + pz * pz;

    float bestd[KK];
    int   besti[KK];
#pragma unroll
    for (int i = 0; i < KK; i++) { bestd[i] = 1e30f; besti[i] = 0; }
    float worst = 1e30f;
    int   wslot = 0;

    for (int m = 0; m < MM; m++) {
        float4 q = sp[m];
        // exact reference formula: |p1|^2 + |p2|^2 - 2 * dot
        float d = n1 + q.w - 2.0f * (px * q.x + py * q.y + pz * q.z);
        if (d < worst) {
            bestd[wslot] = d; besti[wslot] = m;
            worst = bestd[0]; wslot = 0;
#pragma unroll
            for (int i = 1; i < KK; i++)
                if (bestd[i] > worst) { worst = bestd[i]; wslot = i; }
        }
    }
    int* out = g_idx + ((size_t)b * NN + n) * KK;
#pragma unroll
    for (int i = 0; i < KK; i++) out[i] = besti[i];
}

// ---------------------------------------------------------------------------
// Fused: gather(feature2, pos_diff) -> mlp1 (259->128->128->256, BN+ReLU) ->
// max over K. One block = 8 query points * 8 neighbors = 64 columns.
// All activations stay in shared memory. Register-tiled FFMA GEMMs.
// ---------------------------------------------------------------------------
__global__ __launch_bounds__(256) void mlp1_kernel(
    const float* __restrict__ pos1, const float* __restrict__ pos2,
    const float* __restrict__ feature2,
    const float* __restrict__ W0, const float* __restrict__ S0, const float* __restrict__ Bb0,
    const float* __restrict__ W1, const float* __restrict__ S1, const float* __restrict__ Bb1,
    const float* __restrict__ W2, const float* __restrict__ S2, const float* __restrict__ Bb2) {
    extern __shared__ float smem[];
    float* sIn = smem;                 // C0*64 = 16576 floats (reused as layer-1 output)
    float* sH  = smem + C0 * 64;       // H0*64 =  8192 floats
    __shared__ int sidx[64];

    const int b  = blockIdx.y;
    const int n0 = blockIdx.x * 8;
    const int t  = threadIdx.x;

    if (t < 64) sidx[t] = g_idx[((size_t)b * NN + n0 + (t >> 3)) * KK + (t & 7)];
    __syncthreads();

    // gather feature2 channels [0,256)
    const float* f2 = feature2 + (size_t)b * F2C * MM;
    for (int e = t; e < F2C * 64; e += 256) {
        int c = e >> 6, col = e & 63;
        sIn[e] = __ldg(&f2[c * MM + sidx[col]]);
    }
    // pos_diff channels [256,259)
    if (t < 192) {
        int d = t >> 6, col = t & 63;
        float p1v = pos1[((size_t)b * 3 + d) * NN + n0 + (col >> 3)];
        sIn[(F2C + d) * 64 + col] = pos2[((size_t)b * 3 + d) * MM + sidx[col]] - p1v;
    }
    __syncthreads();

    const int cg = t & 7;    // column group: 8 cols = the 8 neighbors of point cg
    const int rg = t >> 3;   // row group (0..31)

    // ---- layer 0: 259 -> 128 ----
    {
        float acc[4][8];
#pragma unroll
        for (int r = 0; r < 4; r++)
#pragma unroll
            for (int j = 0; j < 8; j++) acc[r][j] = 0.0f;

#pragma unroll 2
        for (int c = 0; c < C0; c++) {
            const float4* ip = (const float4*)(sIn + c * 64 + cg * 8);
            float4 a0 = ip[0], a1 = ip[1];
            float in[8] = {a0.x, a0.y, a0.z, a0.w, a1.x, a1.y, a1.z, a1.w};
#pragma unroll
            for (int r = 0; r < 4; r++) {
                float wv = __ldg(&W0[(rg + r * 32) * C0 + c]);
#pragma unroll
                for (int j = 0; j < 8; j++) acc[r][j] = fmaf(wv, in[j], acc[r][j]);
            }
        }
#pragma unroll
        for (int r = 0; r < 4; r++) {
            int o = rg + r * 32;
            float sc = S0[o], bi = Bb0[o];
            float4 v0, v1;
            v0.x = fmaxf(fmaf(acc[r][0], sc, bi), 0.f);
            v0.y = fmaxf(fmaf(acc[r][1], sc, bi), 0.f);
            v0.z = fmaxf(fmaf(acc[r][2], sc, bi), 0.f);
            v0.w = fmaxf(fmaf(acc[r][3], sc, bi), 0.f);
            v1.x = fmaxf(fmaf(acc[r][4], sc, bi), 0.f);
            v1.y = fmaxf(fmaf(acc[r][5], sc, bi), 0.f);
            v1.z = fmaxf(fmaf(acc[r][6], sc, bi), 0.f);
            v1.w = fmaxf(fmaf(acc[r][7], sc, bi), 0.f);
            float4* op = (float4*)(sH + o * 64 + cg * 8);
            op[0] = v0; op[1] = v1;
        }
    }
    __syncthreads();

    // ---- layer 1: 128 -> 128  (reads sH, writes sIn) ----
    {
        float acc[4][8];
#pragma unroll
        for (int r = 0; r < 4; r++)
#pragma unroll
            for (int j = 0; j < 8; j++) acc[r][j] = 0.0f;

#pragma unroll 2
        for (int c = 0; c < H0; c++) {
            const float4* ip = (const float4*)(sH + c * 64 + cg * 8);
            float4 a0 = ip[0], a1 = ip[1];
            float in[8] = {a0.x, a0.y, a0.z, a0.w, a1.x, a1.y, a1.z, a1.w};
#pragma unroll
            for (int r = 0; r < 4; r++) {
                float wv = __ldg(&W1[(rg + r * 32) * H0 + c]);
#pragma unroll
                for (int j = 0; j < 8; j++) acc[r][j] = fmaf(wv, in[j], acc[r][j]);
            }
        }
#pragma unroll
        for (int r = 0; r < 4; r++) {
            int o = rg + r * 32;
            float sc = S1[o], bi = Bb1[o];
            float4 v0, v1;
            v0.x = fmaxf(fmaf(acc[r][0], sc, bi), 0.f);
            v0.y = fmaxf(fmaf(acc[r][1], sc, bi), 0.f);
            v0.z = fmaxf(fmaf(acc[r][2], sc, bi), 0.f);
            v0.w = fmaxf(fmaf(acc[r][3], sc, bi), 0.f);
            v1.x = fmaxf(fmaf(acc[r][4], sc, bi), 0.f);
            v1.y = fmaxf(fmaf(acc[r][5], sc, bi), 0.f);
            v1.z = fmaxf(fmaf(acc[r][6], sc, bi), 0.f);
            v1.w = fmaxf(fmaf(acc[r][7], sc, bi), 0.f);
            float4* op = (float4*)(sIn + o * 64 + cg * 8);   // sH2 = sIn (reuse)
            op[0] = v0; op[1] = v1;
        }
    }
    __syncthreads();

    // ---- layer 2: 128 -> 256, fused max over the 8 neighbors ----
    {
        float acc[8][8];
#pragma unroll
        for (int r = 0; r < 8; r++)
#pragma unroll
            for (int j = 0; j < 8; j++) acc[r][j] = 0.0f;

#pragma unroll 2
        for (int c = 0; c < H1; c++) {
            const float4* ip = (const float4*)(sIn + c * 64 + cg * 8);
            float4 a0 = ip[0], a1 = ip[1];
            float in[8] = {a0.x, a0.y, a0.z, a0.w, a1.x, a1.y, a1.z, a1.w};
#pragma unroll
            for (int r = 0; r < 8; r++) {
                float wv = __ldg(&W2[(rg + r * 32) * H1 + c]);
#pragma unroll
                for (int j = 0; j < 8; j++) acc[r][j] = fmaf(wv, in[j], acc[r][j]);
            }
        }
        // thread's 8 cols are exactly the 8 k-neighbors of point (n0+cg):
        // relu(max(.)) == max(relu(.)) since ReLU is monotone.
#pragma unroll
        for (int r = 0; r < 8; r++) {
            int o = rg + r * 32;
            float sc = S2[o], bi = Bb2[o];
            float m = -1e30f;
#pragma unroll
            for (int j = 0; j < 8; j++) m = fmaxf(m, fmaf(acc[r][j], sc, bi));
            g_mid[((size_t)b * H2 + o) * NN + n0 + cg] = fmaxf(m, 0.0f);
        }
    }
}

// ---------------------------------------------------------------------------
// mlp2: out = relu( W2_0 @ concat(maxpooled, feature1) * s + b ), 512 -> 256.
// One block = 64 columns (n). Input streamed through smem in 64-channel chunks.
// ---------------------------------------------------------------------------
__global__ __launch_bounds__(256) void mlp2_kernel(
    const float* __restrict__ f1, const float* __restrict__ W,
    const float* __restrict__ S, const float* __restrict__ Bi,
    float* __restrict__ out) {
    __shared__ float xT[64 * 64];                        // 16 KB
    const int b  = blockIdx.y;
    const int n0 = blockIdx.x * 64;
    const int t  = threadIdx.x;
    const int cg = t & 7, rg = t >> 3;

    float acc[8][8];
#pragma unroll
    for (int r = 0; r < 8; r++)
#pragma unroll
        for (int j = 0; j < 8; j++) acc[r][j] = 0.0f;

    for (int ch = 0; ch < C2IN; ch += 64) {
        for (int e = t; e < 64 * 64; e += 256) {
            int cc = e >> 6, col = e & 63;
            int c = ch + cc;
            float v = (c < H2) ? g_mid[((size_t)b * H2 + c) * NN + n0 + col]
                               : f1[((size_t)b * F1C + (c - H2)) * NN + n0 + col];
            xT[cc * 64 + col] = v;
        }
        __syncthreads();

#pragma unroll 2
        for (int cc = 0; cc < 64; cc++) {
            const float4* ip = (const float4*)(xT + cc * 64 + cg * 8);
            float4 a0 = ip[0], a1 = ip[1];
            float in[8] = {a0.x, a0.y, a0.z, a0.w, a1.x, a1.y, a1.z, a1.w};
#pragma unroll
            for (int r = 0; r < 8; r++) {
                float wv = __ldg(&W[(rg + r * 32) * C2IN + ch + cc]);
#pragma unroll
                for (int j = 0; j < 8; j++) acc[r][j] = fmaf(wv, in[j], acc[r][j]);
            }
        }
        __syncthreads();
    }

#pragma unroll
    for (int r = 0; r < 8; r++) {
        int o = rg + r * 32;
        float sc = S[o], bi = Bi[o];
#pragma unroll
        for (int j = 0; j < 8; j++)
            out[((size_t)b * C2OUT + o) * NN + n0 + cg * 8 + j] =
                fmaxf(fmaf(acc[r][j], sc, bi), 0.0f);
    }
}

// ---------------------------------------------------------------------------
extern "C" void kernel_launch(void* const* d_in, const int* in_sizes, int n_in,
                              void* d_out, int out_size) {
    const float* pos1     = (const float*)d_in[0];
    const float* pos2     = (const float*)d_in[1];
    const float* feature1 = (const float*)d_in[2];
    const float* feature2 = (const float*)d_in[3];
    const float* w1_0 = (const float*)d_in[4];
    const float* s1_0 = (const float*)d_in[5];
    const float* b1_0 = (const float*)d_in[6];
    const float* w1_1 = (const float*)d_in[7];
    const float* s1_1 = (const float*)d_in[8];
    const float* b1_1 = (const float*)d_in[9];
    const float* w1_2 = (const float*)d_in[10];
    const float* s1_2 = (const float*)d_in[11];
    const float* b1_2 = (const float*)d_in[12];
    const float* w2_0 = (const float*)d_in[13];
    const float* s2_0 = (const float*)d_in[14];
    const float* b2_0 = (const float*)d_in[15];
    float* out = (float*)d_out;

    knn_kernel<<<dim3(NN / 256, BB), 256>>>(pos1, pos2);

    const int smem1 = (C0 * 64 + H0 * 64) * (int)sizeof(float);   // 99072 B
    static int attr_done = 0;
    if (!attr_done) {
        cudaFuncSetAttribute(mlp1_kernel,
                             cudaFuncAttributeMaxDynamicSharedMemorySize, smem1);
        attr_done = 1;
    }
    mlp1_kernel<<<dim3(NN / 8, BB), 256, smem1>>>(
        pos1, pos2, feature2,
        w1_0, s1_0, b1_0, w1_1, s1_1, b1_1, w1_2, s1_2, b1_2);

    mlp2_kernel<<<dim3(NN / 64, BB), 256>>>(feature1, w2_0, s2_0, b2_0, out);
}

// round 3
// speedup vs baseline: 2.2973x; 2.2973x over previous
#include <cuda_runtime.h>
#include <cuda_bf16.h>
#include <mma.h>
#include <cstdint>

using namespace nvcuda;

#define BB 4
#define NN 8192
#define MM 2048
#define KK 8
#define F1C 256
#define F2C 256
#define C0 259
#define H2 256
#define C2IN 512
#define C2OUT 256

// ---------------- scratch (__device__ globals; no allocation allowed) ----------------
__device__ int   g_idx[BB * NN * KK];                       // 1 MB
__device__ float g_mid[(size_t)BB * H2 * NN];               // 32 MB
__device__ float g_y0[(size_t)BB * MM * 128];               // 4 MB  (W0_feat @ feature2, per-point contiguous)
__device__ __align__(16) uint16_t g_w1h[128 * 128], g_w1l[128 * 128];
__device__ __align__(16) uint16_t g_w2h[256 * 128], g_w2l[256 * 128];

__device__ __forceinline__ void split2(float x, uint16_t& h, uint16_t& l) {
    __nv_bfloat16 hb = __float2bfloat16(x);
    __nv_bfloat16 lb = __float2bfloat16(x - __bfloat162float(hb));
    h = __bfloat16_as_ushort(hb);
    l = __bfloat16_as_ushort(lb);
}

// ---------------------------------------------------------------------------
// prep_weights: split W1 (128x128) and W2 (256x128) into bf16 hi/lo, row-major.
// ---------------------------------------------------------------------------
__global__ void prep_weights(const float* __restrict__ W1, const float* __restrict__ W2) {
    int t = blockIdx.x * blockDim.x + threadIdx.x;
    uint16_t h, l;
    if (t < 16384) {
        split2(W1[t], h, l);
        g_w1h[t] = h; g_w1l[t] = l;
    } else if (t < 49152) {
        int i = t - 16384;
        split2(W2[i], h, l);
        g_w2h[i] = h; g_w2l[i] = l;
    }
}

// ---------------------------------------------------------------------------
// y0_kernel: g_y0[b][m][r] = sum_{c<256} W0[r][c] * feature2[b][c][m]   (fp32)
// block = (32 m-points x 128 r-channels), grid (M/32, B)
// ---------------------------------------------------------------------------
__global__ __launch_bounds__(128) void y0_kernel(const float* __restrict__ W0,
                                                 const float* __restrict__ f2) {
    __shared__ float tile[256][33];
    const int b = blockIdx.y, m0 = blockIdx.x * 32, t = threadIdx.x;
    for (int i = t; i < 256 * 32; i += 128) {
        int c = i >> 5, j = i & 31;
        tile[c][j] = f2[((size_t)b * F2C + c) * MM + m0 + j];
    }
    __syncthreads();

    const int r = t;                      // 0..127
    float acc[32];
#pragma unroll
    for (int j = 0; j < 32; j++) acc[j] = 0.0f;
    const float* wrow = W0 + (size_t)r * C0;
#pragma unroll 4
    for (int c = 0; c < 256; c++) {
        float w = __ldg(&wrow[c]);
#pragma unroll
        for (int j = 0; j < 32; j++) acc[j] = fmaf(w, tile[c][j], acc[j]);
    }
    for (int j = 0; j < 32; j++)
        g_y0[((size_t)b * MM + m0 + j) * 128 + r] = acc[j];
}

// ---------------------------------------------------------------------------
// KNN
// ---------------------------------------------------------------------------
__global__ __launch_bounds__(128) void knn_kernel(const float* __restrict__ pos1,
                                                  const float* __restrict__ pos2) {
    __shared__ float4 sp[MM];
    const int b = blockIdx.y;
    const float* p2 = pos2 + (size_t)b * 3 * MM;
    for (int m = threadIdx.x; m < MM; m += blockDim.x) {
        float x = p2[m], y = p2[MM + m], z = p2[2 * MM + m];
        sp[m] = make_float4(x, y, z, x * x + y * y + z * z);
    }
    __syncthreads();

    const int n = blockIdx.x * blockDim.x + threadIdx.x;
    const float* p1 = pos1 + (size_t)b * 3 * NN;
    const float px = p1[n], py = p1[NN + n], pz = p1[2 * NN + n];
    const float n1 = px * px + py * py + pz * pz;

    float bestd[KK]; int besti[KK];
#pragma unroll
    for (int i = 0; i < KK; i++) { bestd[i] = 1e30f; besti[i] = 0; }
    float worst = 1e30f; int wslot = 0;

    for (int m = 0; m < MM; m++) {
        float4 q = sp[m];
        float d = n1 + q.w - 2.0f * (px * q.x + py * q.y + pz * q.z);
        if (d < worst) {
            bestd[wslot] = d; besti[wslot] = m;
            worst = bestd[0]; wslot = 0;
#pragma unroll
            for (int i = 1; i < KK; i++)
                if (bestd[i] > worst) { worst = bestd[i]; wslot = i; }
        }
    }
    int* out = g_idx + ((size_t)b * NN + n) * KK;
#pragma unroll
    for (int i = 0; i < KK; i++) out[i] = besti[i];
}

// ---------------------------------------------------------------------------
// mlp1 via wmma (HMMA): block = 128 columns (16 points x 8 nbrs), 256 threads.
// X planes (col-major, ldm=136) and W planes (row-major, ldm=136) in smem,
// bf16 2-term split, 3 products, fp32 accumulators.
// ---------------------------------------------------------------------------
#define LDX   136
#define OFF_XH 0
#define OFF_XL 34816
#define OFF_WH 69632
#define OFF_WL 104448
#define DSMEM  139264

typedef wmma::fragment<wmma::matrix_a, 16, 16, 16, __nv_bfloat16, wmma::row_major> frag_a;
typedef wmma::fragment<wmma::matrix_b, 16, 16, 16, __nv_bfloat16, wmma::col_major> frag_b;
typedef wmma::fragment<wmma::accumulator, 16, 16, 16, float> frag_c;

__device__ __forceinline__ void gemm_split(const char* smp, int m0, frag_c c[8]) {
    const __nv_bfloat16* Wh = (const __nv_bfloat16*)(smp + OFF_WH);
    const __nv_bfloat16* Wl = (const __nv_bfloat16*)(smp + OFF_WL);
    const __nv_bfloat16* Xh = (const __nv_bfloat16*)(smp + OFF_XH);
    const __nv_bfloat16* Xl = (const __nv_bfloat16*)(smp + OFF_XL);
#pragma unroll
    for (int nt = 0; nt < 8; nt++) wmma::fill_fragment(c[nt], 0.0f);
    for (int k0 = 0; k0 < 128; k0 += 16) {
        frag_a ah, al;
        wmma::load_matrix_sync(ah, Wh + m0 * LDX + k0, LDX);
        wmma::load_matrix_sync(al, Wl + m0 * LDX + k0, LDX);
#pragma unroll
        for (int nt = 0; nt < 8; nt++) {
            frag_b bh, bl;
            wmma::load_matrix_sync(bh, Xh + nt * 16 * LDX + k0, LDX);
            wmma::mma_sync(c[nt], ah, bh, c[nt]);
            wmma::load_matrix_sync(bl, Xl + nt * 16 * LDX + k0, LDX);
            wmma::mma_sync(c[nt], ah, bl, c[nt]);
            wmma::mma_sync(c[nt], al, bh, c[nt]);
        }
    }
}

__device__ __forceinline__ void load_w(const char* smp, const uint16_t* gh, const uint16_t* gl, int t) {
    const uint4* sh = (const uint4*)gh;
    const uint4* sl = (const uint4*)gl;
    uint4* dh = (uint4*)(smp + OFF_WH);
    uint4* dl = (uint4*)(smp + OFF_WL);
    for (int i = t; i < 2048; i += 256) {
        int row = i >> 4, q = i & 15;
        dh[row * 17 + q] = sh[i];
        dl[row * 17 + q] = sl[i];
    }
}

__global__ __launch_bounds__(256, 1) void mlp1_wmma(
    const float* __restrict__ pos1, const float* __restrict__ pos2,
    const float* __restrict__ W0full,
    const float* __restrict__ S0, const float* __restrict__ B0,
    const float* __restrict__ S1, const float* __restrict__ B1,
    const float* __restrict__ S2, const float* __restrict__ B2) {
    extern __shared__ __align__(16) char smp[];
    __shared__ int sidx[128];
    __shared__ float sw0pos[3 * 128];

    const int t = threadIdx.x, wid = t >> 5, lid = t & 31;
    const int b = blockIdx.y, n0 = blockIdx.x * 16;
    const int m0 = wid * 16;

    if (t < 128) sidx[t] = g_idx[((size_t)b * NN + n0 + (t >> 3)) * KK + (t & 7)];
    for (int i = t; i < 384; i += 256) {
        int d = i >> 7, r = i & 127;
        sw0pos[i] = W0full[(size_t)r * C0 + 256 + d];
    }
    __syncthreads();

    // ---- epilogue 0: gather y0, add pos correction, BN+ReLU, split -> X1 ----
    {
        int col = t >> 1, half = t & 1;
        int m = sidx[col], n = n0 + (col >> 3);
        float pd0 = pos2[((size_t)b * 3 + 0) * MM + m] - pos1[((size_t)b * 3 + 0) * NN + n];
        float pd1 = pos2[((size_t)b * 3 + 1) * MM + m] - pos1[((size_t)b * 3 + 1) * NN + n];
        float pd2 = pos2[((size_t)b * 3 + 2) * MM + m] - pos1[((size_t)b * 3 + 2) * NN + n];
        const float4* yb = (const float4*)(g_y0 + ((size_t)b * MM + m) * 128 + half * 64);
        uint32_t* XH32 = (uint32_t*)(smp + OFF_XH);
        uint32_t* XL32 = (uint32_t*)(smp + OFF_XL);
#pragma unroll
        for (int i = 0; i < 16; i++) {
            float4 v = yb[i];
            float vv[4] = {v.x, v.y, v.z, v.w};
            uint16_t hh[4], ll[4];
#pragma unroll
            for (int j = 0; j < 4; j++) {
                int r = half * 64 + i * 4 + j;
                float acc = vv[j] + pd0 * sw0pos[r] + pd1 * sw0pos[128 + r] + pd2 * sw0pos[256 + r];
                float y = fmaxf(fmaf(acc, __ldg(&S0[r]), __ldg(&B0[r])), 0.0f);
                split2(y, hh[j], ll[j]);
            }
            int e2 = (col * LDX + half * 64 + i * 4) >> 1;
            XH32[e2]     = (uint32_t)hh[0] | ((uint32_t)hh[1] << 16);
            XH32[e2 + 1] = (uint32_t)hh[2] | ((uint32_t)hh[3] << 16);
            XL32[e2]     = (uint32_t)ll[0] | ((uint32_t)ll[1] << 16);
            XL32[e2 + 1] = (uint32_t)ll[2] | ((uint32_t)ll[3] << 16);
        }
    }
    load_w(smp, g_w1h, g_w1l, t);
    __syncthreads();

    float* scr = (float*)(smp + OFF_WH) + wid * 2048;   // 16x128 fp32, warp-private

    // ---- layer 1 ----
    {
        frag_c c[8];
        gemm_split(smp, m0, c);
        __syncthreads();                                  // all reads of X1/W1 done
#pragma unroll
        for (int nt = 0; nt < 8; nt++)
            wmma::store_matrix_sync(scr + nt * 16, c[nt], 128, wmma::mem_row_major);
        __syncwarp();
        uint32_t* XH32 = (uint32_t*)(smp + OFF_XH);
        uint32_t* XL32 = (uint32_t*)(smp + OFF_XL);
#pragma unroll
        for (int cc = 0; cc < 4; cc++) {
            int col = (lid << 2) | cc;
#pragma unroll
            for (int r = 0; r < 16; r += 2) {
                float y0v = fmaxf(fmaf(scr[r * 128 + col],       __ldg(&S1[m0 + r]),     __ldg(&B1[m0 + r])), 0.0f);
                float y1v = fmaxf(fmaf(scr[(r + 1) * 128 + col], __ldg(&S1[m0 + r + 1]), __ldg(&B1[m0 + r + 1])), 0.0f);
                uint16_t h0, l0, h1, l1;
                split2(y0v, h0, l0); split2(y1v, h1, l1);
                int e2 = (col * LDX + m0 + r) >> 1;
                XH32[e2] = (uint32_t)h0 | ((uint32_t)h1 << 16);
                XL32[e2] = (uint32_t)l0 | ((uint32_t)l1 << 16);
            }
        }
    }
    __syncthreads();

    // ---- layer 2: two 128-row halves of W2 ----
    for (int h = 0; h < 2; h++) {
        load_w(smp, g_w2h + h * 16384, g_w2l + h * 16384, t);
        __syncthreads();
        frag_c c[8];
        gemm_split(smp, m0, c);
        __syncthreads();
#pragma unroll
        for (int nt = 0; nt < 8; nt++)
            wmma::store_matrix_sync(scr + nt * 16, c[nt], 128, wmma::mem_row_major);
        __syncwarp();
        // BN + max over 8 neighbors + ReLU -> g_mid
        int pt = lid & 15, rb = (lid >> 4) * 8;
#pragma unroll
        for (int rr = 0; rr < 8; rr++) {
            int r = rb + rr, o = h * 128 + m0 + r;
            float sc = __ldg(&S2[o]), bi = __ldg(&B2[o]);
            float mx = -1e30f;
#pragma unroll
            for (int j = 0; j < 8; j++)
                mx = fmaxf(mx, fmaf(scr[r * 128 + pt * 8 + j], sc, bi));
            g_mid[((size_t)b * H2 + o) * NN + n0 + pt] = fmaxf(mx, 0.0f);
        }
        __syncthreads();                                  // before next W load over scratch
    }
}

// ---------------------------------------------------------------------------
// mlp2 (FFMA): out = relu(W @ concat(g_mid, feature1) * s + b), 512 -> 256
// ---------------------------------------------------------------------------
__global__ __launch_bounds__(256) void mlp2_kernel(
    const float* __restrict__ f1, const float* __restrict__ W,
    const float* __restrict__ S, const float* __restrict__ Bi,
    float* __restrict__ out) {
    __shared__ float xT[64 * 64];
    const int b = blockIdx.y, n0 = blockIdx.x * 64, t = threadIdx.x;
    const int cg = t & 7, rg = t >> 3;

    float acc[8][8];
#pragma unroll
    for (int r = 0; r < 8; r++)
#pragma unroll
        for (int j = 0; j < 8; j++) acc[r][j] = 0.0f;

    for (int ch = 0; ch < C2IN; ch += 64) {
        for (int e = t; e < 64 * 64; e += 256) {
            int cc = e >> 6, col = e & 63;
            int c = ch + cc;
            float v = (c < H2) ? g_mid[((size_t)b * H2 + c) * NN + n0 + col]
                               : f1[((size_t)b * F1C + (c - H2)) * NN + n0 + col];
            xT[cc * 64 + col] = v;
        }
        __syncthreads();
#pragma unroll 2
        for (int cc = 0; cc < 64; cc++) {
            const float4* ip = (const float4*)(xT + cc * 64 + cg * 8);
            float4 a0 = ip[0], a1 = ip[1];
            float in[8] = {a0.x, a0.y, a0.z, a0.w, a1.x, a1.y, a1.z, a1.w};
#pragma unroll
            for (int r = 0; r < 8; r++) {
                float wv = __ldg(&W[(rg + r * 32) * C2IN + ch + cc]);
#pragma unroll
                for (int j = 0; j < 8; j++) acc[r][j] = fmaf(wv, in[j], acc[r][j]);
            }
        }
        __syncthreads();
    }
#pragma unroll
    for (int r = 0; r < 8; r++) {
        int o = rg + r * 32;
        float sc = S[o], bi = Bi[o];
#pragma unroll
        for (int j = 0; j < 8; j++)
            out[((size_t)b * C2OUT + o) * NN + n0 + cg * 8 + j] =
                fmaxf(fmaf(acc[r][j], sc, bi), 0.0f);
    }
}

// ---------------------------------------------------------------------------
extern "C" void kernel_launch(void* const* d_in, const int* in_sizes, int n_in,
                              void* d_out, int out_size) {
    const float* pos1     = (const float*)d_in[0];
    const float* pos2     = (const float*)d_in[1];
    const float* feature1 = (const float*)d_in[2];
    const float* feature2 = (const float*)d_in[3];
    const float* w1_0 = (const float*)d_in[4];
    const float* s1_0 = (const float*)d_in[5];
    const float* b1_0 = (const float*)d_in[6];
    const float* w1_1 = (const float*)d_in[7];
    const float* s1_1 = (const float*)d_in[8];
    const float* b1_1 = (const float*)d_in[9];
    const float* w1_2 = (const float*)d_in[10];
    const float* s1_2 = (const float*)d_in[11];
    const float* b1_2 = (const float*)d_in[12];
    const float* w2_0 = (const float*)d_in[13];
    const float* s2_0 = (const float*)d_in[14];
    const float* b2_0 = (const float*)d_in[15];
    float* out = (float*)d_out;

    static int attr_done = 0;
    if (!attr_done) {
        cudaFuncSetAttribute(mlp1_wmma, cudaFuncAttributeMaxDynamicSharedMemorySize, DSMEM);
        attr_done = 1;
    }

    prep_weights<<<192, 256>>>(w1_1, w1_2);
    y0_kernel<<<dim3(MM / 32, BB), 128>>>(w1_0, feature2);
    knn_kernel<<<dim3(NN / 128, BB), 128>>>(pos1, pos2);
    mlp1_wmma<<<dim3(NN / 16, BB), 256, DSMEM>>>(pos1, pos2, w1_0,
                                                 s1_0, b1_0, s1_1, b1_1, s1_2, b1_2);
    mlp2_kernel<<<dim3(NN / 64, BB), 256>>>(feature1, w2_0, s2_0, b2_0, out);
}

// round 5
// speedup vs baseline: 5.2205x; 2.2725x over previous
#include <cuda_runtime.h>
#include <cuda_fp16.h>
#include <mma.h>
#include <cstdint>

using namespace nvcuda;

#define BB 4
#define NN 8192
#define MM 2048
#define KK 8
#define F1C 256
#define F2C 256
#define C0 259
#define H2 256
#define C2IN 512
#define MS 4
#define MCH (MM / MS)

// ---------------- scratch (__device__ globals) ----------------
__device__ int   g_idx[BB * NN * KK];
__device__ float g_y0[(size_t)BB * MM * 128];                      // W0_feat @ feature2 (per-point contiguous)
__device__ __half g_midh[(size_t)BB * H2 * NN];                    // mlp1 output (fp16)
__device__ __align__(16) uint16_t g_w1h[128 * 128];
__device__ __align__(16) uint16_t g_w2h[256 * 128];
__device__ __align__(16) uint16_t g_w20h[256 * 512];
__device__ __align__(16) uint16_t g_f1h[(size_t)BB * F1C * NN];
__device__ float g_cd[(size_t)BB * NN * 32];
__device__ int   g_ci[(size_t)BB * NN * 32];

__device__ __forceinline__ uint16_t f2h(float x) {
    return __half_as_ushort(__float2half_rn(x));
}

// ---------------------------------------------------------------------------
// prep: convert weights + feature1 to fp16
// ---------------------------------------------------------------------------
__global__ void prep_kernel(const float* __restrict__ W1, const float* __restrict__ W2,
                            const float* __restrict__ W20, const float* __restrict__ F1) {
    int64_t t = (int64_t)blockIdx.x * blockDim.x + threadIdx.x;
    if (t < 16384) {
        g_w1h[t] = f2h(W1[t]);
    } else if (t < 49152) {
        int i = t - 16384;
        g_w2h[i] = f2h(W2[i]);
    } else if (t < 180224) {
        int i = t - 49152;
        g_w20h[i] = f2h(W20[i]);
    } else {
        int64_t i = t - 180224;
        if (i < (int64_t)BB * F1C * NN)
            g_f1h[i] = f2h(F1[i]);
    }
}

// ---------------------------------------------------------------------------
// y0: g_y0[b][m][r] = sum_c W0[r][c] * feature2[b][c][m]   (fp32, exact)
// ---------------------------------------------------------------------------
__global__ __launch_bounds__(128) void y0_kernel(const float* __restrict__ W0,
                                                 const float* __restrict__ f2) {
    __shared__ float tile[256][33];
    const int b = blockIdx.y, m0 = blockIdx.x * 32, t = threadIdx.x;
    for (int i = t; i < 256 * 32; i += 128) {
        int c = i >> 5, j = i & 31;
        tile[c][j] = f2[((size_t)b * F2C + c) * MM + m0 + j];
    }
    __syncthreads();
    const int r = t;
    float acc[32];
#pragma unroll
    for (int j = 0; j < 32; j++) acc[j] = 0.0f;
    const float* wrow = W0 + (size_t)r * C0;
#pragma unroll 4
    for (int c = 0; c < 256; c++) {
        float w = __ldg(&wrow[c]);
#pragma unroll
        for (int j = 0; j < 32; j++) acc[j] = fmaf(w, tile[c][j], acc[j]);
    }
    for (int j = 0; j < 32; j++)
        g_y0[((size_t)b * MM + m0 + j) * 128 + r] = acc[j];
}

// ---------------------------------------------------------------------------
// KNN scan: each block scans MCH pos2 points for 128 queries, keeps top-8.
// ---------------------------------------------------------------------------
__global__ __launch_bounds__(128) void knn_scan(const float* __restrict__ pos1,
                                                const float* __restrict__ pos2) {
    __shared__ float4 sp[MCH];
    const int b = blockIdx.z, ms = blockIdx.y, mb = ms * MCH;
    const float* p2 = pos2 + (size_t)b * 3 * MM;
    for (int m = threadIdx.x; m < MCH; m += 128) {
        int gm = mb + m;
        float x = p2[gm], y = p2[MM + gm], z = p2[2 * MM + gm];
        sp[m] = make_float4(x, y, z, x * x + y * y + z * z);
    }
    __syncthreads();

    const int n = blockIdx.x * 128 + threadIdx.x;
    const float* p1 = pos1 + (size_t)b * 3 * NN;
    const float px = p1[n], py = p1[NN + n], pz = p1[2 * NN + n];
    const float n1 = px * px + py * py + pz * pz;

    float bestd[KK]; int besti[KK];
#pragma unroll
    for (int i = 0; i < KK; i++) { bestd[i] = 1e30f; besti[i] = mb; }
    float worst = 1e30f; int wslot = 0;

    for (int m = 0; m < MCH; m++) {
        float4 q = sp[m];
        float d = n1 + q.w - 2.0f * (px * q.x + py * q.y + pz * q.z);
        if (d < worst) {
            bestd[wslot] = d; besti[wslot] = mb + m;
            worst = bestd[0]; wslot = 0;
#pragma unroll
            for (int i = 1; i < KK; i++)
                if (bestd[i] > worst) { worst = bestd[i]; wslot = i; }
        }
    }
    size_t base = ((size_t)b * NN + n) * 32 + ms * 8;
#pragma unroll
    for (int i = 0; i < KK; i++) { g_cd[base + i] = bestd[i]; g_ci[base + i] = besti[i]; }
}

// ---------------------------------------------------------------------------
// KNN merge: top-8 of 32 candidates, (d, idx) lexicographic.
// ---------------------------------------------------------------------------
__global__ __launch_bounds__(128) void knn_merge() {
    const int n = blockIdx.x * 128 + threadIdx.x, b = blockIdx.y;
    size_t base = ((size_t)b * NN + n) * 32;
    float cd[32]; int ci[32];
#pragma unroll
    for (int j = 0; j < 32; j++) { cd[j] = g_cd[base + j]; ci[j] = g_ci[base + j]; }
    int* out = g_idx + ((size_t)b * NN + n) * 8;
#pragma unroll
    for (int s = 0; s < 8; s++) {
        float dm = 1e38f; int im = 0x7fffffff, jm = 0;
#pragma unroll
        for (int j = 0; j < 32; j++) {
            bool bt = (cd[j] < dm) || (cd[j] == dm && ci[j] < im);
            if (bt) { dm = cd[j]; im = ci[j]; jm = j; }
        }
        out[s] = im;
#pragma unroll
        for (int j = 0; j < 32; j++)
            if (j == jm) cd[j] = 1e38f;
    }
}

// ---------------------------------------------------------------------------
// mlp1 (wmma fp16, single product): block = 128 cols (16 points x 8 nbrs).
// ---------------------------------------------------------------------------
#define LDX 136
#define OFF_X 0
#define OFF_W 34816
#define OFF_SCR 69632
#define OFF_STAGE 79872
#define DSMEM1 88064

typedef wmma::fragment<wmma::matrix_a, 16, 16, 16, __half, wmma::row_major> frag_a;
typedef wmma::fragment<wmma::matrix_b, 16, 16, 16, __half, wmma::col_major> frag_bc;
typedef wmma::fragment<wmma::matrix_b, 16, 16, 16, __half, wmma::row_major> frag_br;
typedef wmma::fragment<wmma::accumulator, 16, 16, 16, float> frag_c;

__device__ __forceinline__ void load_w128(char* smp, const uint16_t* gh, int t) {
    const uint4* s = (const uint4*)gh;
    uint4* d = (uint4*)(smp + OFF_W);
    for (int i = t; i < 2048; i += 256) d[(i >> 4) * 17 + (i & 15)] = s[i];
}

__device__ __forceinline__ void gemm1(const char* smp, int mw, int nw, frag_c c[2][4]) {
    const __half* Wp = (const __half*)(smp + OFF_W);
    const __half* Xp = (const __half*)(smp + OFF_X);
#pragma unroll
    for (int mi = 0; mi < 2; mi++)
#pragma unroll
        for (int nt = 0; nt < 4; nt++) wmma::fill_fragment(c[mi][nt], 0.0f);
    for (int k0 = 0; k0 < 128; k0 += 16) {
        frag_a a0, a1;
        wmma::load_matrix_sync(a0, Wp + (mw * 32) * LDX + k0, LDX);
        wmma::load_matrix_sync(a1, Wp + (mw * 32 + 16) * LDX + k0, LDX);
#pragma unroll
        for (int nt = 0; nt < 4; nt++) {
            frag_bc bb;
            wmma::load_matrix_sync(bb, Xp + (nw * 64 + nt * 16) * LDX + k0, LDX);
            wmma::mma_sync(c[0][nt], a0, bb, c[0][nt]);
            wmma::mma_sync(c[1][nt], a1, bb, c[1][nt]);
        }
    }
}

__global__ __launch_bounds__(256, 2) void mlp1_wmma(
    const float* __restrict__ pos1, const float* __restrict__ pos2,
    const float* __restrict__ W0full,
    const float* __restrict__ S0, const float* __restrict__ B0,
    const float* __restrict__ S1, const float* __restrict__ B1,
    const float* __restrict__ S2, const float* __restrict__ B2) {
    extern __shared__ __align__(32) char smp[];
    __shared__ int sidx[128];
    __shared__ float sw0pos[3 * 128];

    const int t = threadIdx.x, wid = t >> 5, lid = t & 31;
    const int mw = wid & 3, nw = wid >> 2;
    const int b = blockIdx.y, n0 = blockIdx.x * 16;

    if (t < 128) sidx[t] = g_idx[((size_t)b * NN + n0 + (t >> 3)) * KK + (t & 7)];
    for (int i = t; i < 384; i += 256) {
        int d = i >> 7, r = i & 127;
        sw0pos[i] = W0full[(size_t)r * C0 + 256 + d];
    }
    __syncthreads();

    // ---- epilogue 0: gather y0 + pos correction, BN+ReLU -> X (fp16) ----
    {
        int col = t >> 1, half = t & 1;
        int m = sidx[col], n = n0 + (col >> 3);
        float pd0 = pos2[((size_t)b * 3 + 0) * MM + m] - pos1[((size_t)b * 3 + 0) * NN + n];
        float pd1 = pos2[((size_t)b * 3 + 1) * MM + m] - pos1[((size_t)b * 3 + 1) * NN + n];
        float pd2 = pos2[((size_t)b * 3 + 2) * MM + m] - pos1[((size_t)b * 3 + 2) * NN + n];
        const float4* yb = (const float4*)(g_y0 + ((size_t)b * MM + m) * 128 + half * 64);
        uint32_t* X32 = (uint32_t*)(smp + OFF_X);
#pragma unroll
        for (int i = 0; i < 16; i++) {
            float4 v = yb[i];
            float vv[4] = {v.x, v.y, v.z, v.w};
            uint16_t hh[4];
#pragma unroll
            for (int j = 0; j < 4; j++) {
                int r = half * 64 + i * 4 + j;
                float acc = vv[j] + pd0 * sw0pos[r] + pd1 * sw0pos[128 + r] + pd2 * sw0pos[256 + r];
                float y = fmaxf(fmaf(acc, __ldg(&S0[r]), __ldg(&B0[r])), 0.0f);
                hh[j] = f2h(y);
            }
            int e2 = (col * LDX + half * 64 + i * 4) >> 1;
            X32[e2]     = (uint32_t)hh[0] | ((uint32_t)hh[1] << 16);
            X32[e2 + 1] = (uint32_t)hh[2] | ((uint32_t)hh[3] << 16);
        }
    }
    load_w128(smp, g_w1h, t);
    __syncthreads();

    float* scr = (float*)(smp + OFF_SCR) + wid * 320;       // 16x20 fp32 warp-private
    uint16_t* stage = (uint16_t*)(smp + OFF_STAGE);          // [256][16] fp16
    uint16_t* Xb = (uint16_t*)(smp + OFF_X);

    // ---- layer 1: 128 -> 128 ----
    {
        frag_c c[2][4];
        gemm1(smp, mw, nw, c);
        __syncthreads();                                     // X0/W1 reads done
#pragma unroll
        for (int mi = 0; mi < 2; mi++)
#pragma unroll
            for (int nt = 0; nt < 4; nt++) {
                wmma::store_matrix_sync(scr, c[mi][nt], 20, wmma::mem_row_major);
                __syncwarp();
                int r = lid & 15, ch2 = lid >> 4;
                int rowg = mw * 32 + mi * 16 + r;
                float sc = __ldg(&S1[rowg]), bi = __ldg(&B1[rowg]);
#pragma unroll
                for (int j = 0; j < 8; j++) {
                    int colin = ch2 * 8 + j;
                    float y = fmaxf(fmaf(scr[r * 20 + colin], sc, bi), 0.0f);
                    int colg = nw * 64 + nt * 16 + colin;
                    Xb[colg * LDX + rowg] = f2h(y);
                }
                __syncwarp();
            }
    }

    // ---- layer 2: 256 rows in two halves; maxpool over 8 nbrs -> stage ----
    for (int h = 0; h < 2; h++) {
        __syncthreads();                                     // X1 writes / prior epilogue done
        load_w128(smp, g_w2h + h * 16384, t);
        __syncthreads();
        frag_c c[2][4];
        gemm1(smp, mw, nw, c);
        __syncthreads();                                     // W reads done (before next overwrite)
#pragma unroll
        for (int mi = 0; mi < 2; mi++)
#pragma unroll
            for (int nt = 0; nt < 4; nt++) {
                wmma::store_matrix_sync(scr, c[mi][nt], 20, wmma::mem_row_major);
                __syncwarp();
                int r = lid & 15, pt = lid >> 4;
                int rowg = mw * 32 + mi * 16 + r;
                int o = h * 128 + rowg;
                float sc = __ldg(&S2[o]), bi = __ldg(&B2[o]);
                float mx = -1e30f;
#pragma unroll
                for (int j = 0; j < 8; j++)
                    mx = fmaxf(mx, fmaf(scr[r * 20 + pt * 8 + j], sc, bi));
                stage[o * 16 + (nw * 8 + nt * 2 + pt)] = f2h(fmaxf(mx, 0.0f));
                __syncwarp();
            }
    }
    __syncthreads();
    // stage -> g_midh (32B per row)
    if (t < 256) {
        const uint4* s = (const uint4*)(stage + t * 16);
        uint4* d = (uint4*)(&g_midh[((size_t)b * H2 + t) * NN + n0]);
        d[0] = s[0]; d[1] = s[1];
    }
}

// ---------------------------------------------------------------------------
// mlp2 (wmma fp16): out = relu(W20 @ concat(g_midh, f1h) * s + b), 512 -> 256.
// Block: 128 rows x 128 cols, K chunked by 128.
// ---------------------------------------------------------------------------
#define DSMEM2 79872

__global__ __launch_bounds__(256, 2) void mlp2_wmma(
    const float* __restrict__ S, const float* __restrict__ Bi,
    float* __restrict__ out) {
    extern __shared__ __align__(32) char smp[];
    const int t = threadIdx.x, wid = t >> 5, lid = t & 31;
    const int mw = wid & 3, nw = wid >> 2;
    const int b = blockIdx.z, m0b = blockIdx.y * 128, n0 = blockIdx.x * 128;

    uint16_t* Xc = (uint16_t*)(smp + OFF_X);
    uint16_t* Wc = (uint16_t*)(smp + OFF_W);
    float* scr = (float*)(smp + OFF_SCR) + wid * 320;

    frag_c c[2][4];
#pragma unroll
    for (int mi = 0; mi < 2; mi++)
#pragma unroll
        for (int nt = 0; nt < 4; nt++) wmma::fill_fragment(c[mi][nt], 0.0f);

    for (int ch = 0; ch < C2IN; ch += 128) {
        // W chunk
        {
            uint4* d = (uint4*)Wc;
            for (int i = t; i < 2048; i += 256) {
                int row = i >> 4, q = i & 15;
                d[row * 17 + q] = ((const uint4*)(g_w20h + (size_t)(m0b + row) * 512 + ch))[q];
            }
        }
        // X chunk (row-major [k][n])
        {
            uint4* d = (uint4*)Xc;
            const uint16_t* src = (ch < 256)
                ? (const uint16_t*)&g_midh[((size_t)b * H2 + ch) * NN + n0]
                : &g_f1h[((size_t)b * F1C + (ch - 256)) * NN + n0];
            for (int i = t; i < 2048; i += 256) {
                int row = i >> 4, q = i & 15;
                d[row * 17 + q] = ((const uint4*)(src + (size_t)row * NN))[q];
            }
        }
        __syncthreads();
        const __half* Wp = (const __half*)Wc;
        const __half* Xp = (const __half*)Xc;
        for (int k0 = 0; k0 < 128; k0 += 16) {
            frag_a a0, a1;
            wmma::load_matrix_sync(a0, Wp + (mw * 32) * LDX + k0, LDX);
            wmma::load_matrix_sync(a1, Wp + (mw * 32 + 16) * LDX + k0, LDX);
#pragma unroll
            for (int nt = 0; nt < 4; nt++) {
                frag_br bb;
                wmma::load_matrix_sync(bb, Xp + k0 * LDX + (nw * 64 + nt * 16), LDX);
                wmma::mma_sync(c[0][nt], a0, bb, c[0][nt]);
                wmma::mma_sync(c[1][nt], a1, bb, c[1][nt]);
            }
        }
        __syncthreads();
    }

#pragma unroll
    for (int mi = 0; mi < 2; mi++)
#pragma unroll
        for (int nt = 0; nt < 4; nt++) {
            wmma::store_matrix_sync(scr, c[mi][nt], 20, wmma::mem_row_major);
            __syncwarp();
            int colin = lid & 15, rh = lid >> 4;
            int o = m0b + mw * 32 + mi * 16;
            int colg = n0 + nw * 64 + nt * 16 + colin;
#pragma unroll
            for (int j = 0; j < 8; j++) {
                int r = rh * 8 + j;
                float y = fmaxf(fmaf(scr[r * 20 + colin], __ldg(&S[o + r]), __ldg(&Bi[o + r])), 0.0f);
                out[((size_t)b * H2 + o + r) * NN + colg] = y;
            }
            __syncwarp();
        }
}

// ---------------------------------------------------------------------------
extern "C" void kernel_launch(void* const* d_in, const int* in_sizes, int n_in,
                              void* d_out, int out_size) {
    const float* pos1     = (const float*)d_in[0];
    const float* pos2     = (const float*)d_in[1];
    const float* feature1 = (const float*)d_in[2];
    const float* feature2 = (const float*)d_in[3];
    const float* w1_0 = (const float*)d_in[4];
    const float* s1_0 = (const float*)d_in[5];
    const float* b1_0 = (const float*)d_in[6];
    const float* w1_1 = (const float*)d_in[7];
    const float* s1_1 = (const float*)d_in[8];
    const float* b1_1 = (const float*)d_in[9];
    const float* w1_2 = (const float*)d_in[10];
    const float* s1_2 = (const float*)d_in[11];
    const float* b1_2 = (const float*)d_in[12];
    const float* w2_0 = (const float*)d_in[13];
    const float* s2_0 = (const float*)d_in[14];
    const float* b2_0 = (const float*)d_in[15];
    float* out = (float*)d_out;

    static int attr_done = 0;
    if (!attr_done) {
        cudaFuncSetAttribute(mlp1_wmma, cudaFuncAttributeMaxDynamicSharedMemorySize, DSMEM1);
        cudaFuncSetAttribute(mlp2_wmma, cudaFuncAttributeMaxDynamicSharedMemorySize, DSMEM2);
        attr_done = 1;
    }

    prep_kernel<<<33472, 256>>>(w1_1, w1_2, w2_0, feature1);
    y0_kernel<<<dim3(MM / 32, BB), 128>>>(w1_0, feature2);
    knn_scan<<<dim3(NN / 128, MS, BB), 128>>>(pos1, pos2);
    knn_merge<<<dim3(NN / 128, BB), 128>>>();
    mlp1_wmma<<<dim3(NN / 16, BB), 256, DSMEM1>>>(pos1, pos2, w1_0,
                                                  s1_0, b1_0, s1_1, b1_1, s1_2, b1_2);
    mlp2_wmma<<<dim3(NN / 128, 2, BB), 256, DSMEM2>>>(s2_0, b2_0, out);
}

// round 6
// speedup vs baseline: 5.5099x; 1.0554x over previous
#include <cuda_runtime.h>
#include <cuda_fp16.h>
#include <mma.h>
#include <cstdint>

using namespace nvcuda;

#define BB 4
#define NN 8192
#define MM 2048
#define KK 8
#define F1C 256
#define F2C 256
#define C0 259
#define H2 256
#define C2IN 512
#define MS 2
#define MCH (MM / MS)

// ---------------- scratch (__device__ globals) ----------------
__device__ float g_y0[(size_t)BB * MM * 128];                      // s0 * (W0_feat @ feature2)
__device__ __half g_midh[(size_t)BB * H2 * NN];                    // mlp1 output (fp16)
__device__ __align__(16) uint16_t g_w1h[128 * 128];
__device__ __align__(16) uint16_t g_w2h[256 * 128];
__device__ __align__(16) uint16_t g_w20h[256 * 512];
__device__ float g_cd[(size_t)BB * NN * 16];
__device__ int   g_ci[(size_t)BB * NN * 16];

__device__ __forceinline__ uint16_t f2h(float x) {
    return __half_as_ushort(__float2half_rn(x));
}
__device__ __forceinline__ uint32_t smem_u32(const void* p) {
    uint32_t a;
    asm("{ .reg .u64 t; cvta.to.shared.u64 t, %1; cvt.u32.u64 %0, t; }" : "=r"(a) : "l"(p));
    return a;
}

// ---------------------------------------------------------------------------
// prep: weights -> fp16 with BN scale folded in (W' = diag(s) W)
// ---------------------------------------------------------------------------
__global__ void prep_kernel(const float* __restrict__ W1, const float* __restrict__ S1,
                            const float* __restrict__ W2, const float* __restrict__ S2,
                            const float* __restrict__ W20, const float* __restrict__ S20) {
    int t = blockIdx.x * blockDim.x + threadIdx.x;
    if (t < 16384) {
        g_w1h[t] = f2h(W1[t] * __ldg(&S1[t >> 7]));
    } else if (t < 49152) {
        int i = t - 16384;
        g_w2h[i] = f2h(W2[i] * __ldg(&S2[i >> 7]));
    } else if (t < 180224) {
        int i = t - 49152;
        g_w20h[i] = f2h(W20[i] * __ldg(&S20[i >> 9]));
    }
}

// ---------------------------------------------------------------------------
// y0: g_y0[b][m][r] = S0[r] * sum_c W0[r][c] * feature2[b][c][m]   (fp32)
// ---------------------------------------------------------------------------
__global__ __launch_bounds__(128) void y0_kernel(const float* __restrict__ W0,
                                                 const float* __restrict__ S0,
                                                 const float* __restrict__ f2) {
    __shared__ float tile[256][33];
    const int b = blockIdx.y, m0 = blockIdx.x * 32, t = threadIdx.x;
    for (int i = t; i < 256 * 32; i += 128) {
        int c = i >> 5, j = i & 31;
        tile[c][j] = f2[((size_t)b * F2C + c) * MM + m0 + j];
    }
    __syncthreads();
    const int r = t;
    float acc[32];
#pragma unroll
    for (int j = 0; j < 32; j++) acc[j] = 0.0f;
    const float* wrow = W0 + (size_t)r * C0;
#pragma unroll 4
    for (int c = 0; c < 256; c++) {
        float w = __ldg(&wrow[c]);
#pragma unroll
        for (int j = 0; j < 32; j++) acc[j] = fmaf(w, tile[c][j], acc[j]);
    }
    float s0 = __ldg(&S0[r]);
    for (int j = 0; j < 32; j++)
        g_y0[((size_t)b * MM + m0 + j) * 128 + r] = acc[j] * s0;
}

// ---------------------------------------------------------------------------
// KNN scan with packed f32x2 FMA: 4 points/iteration, top-8 per chunk.
// smem: point pairs as [pair]{x0,x1,y0,y1} and [pair]{z0,z1,w0,w1}.
// ---------------------------------------------------------------------------
__global__ __launch_bounds__(128) void knn_scan(const float* __restrict__ pos1,
                                                const float* __restrict__ pos2) {
    __shared__ __align__(16) float sXY[MCH * 2];
    __shared__ __align__(16) float sZW[MCH * 2];
    const int b = blockIdx.z, ms = blockIdx.y, mb = ms * MCH;
    const float* p2 = pos2 + (size_t)b * 3 * MM;
    for (int m = threadIdx.x; m < MCH; m += 128) {
        int gm = mb + m;
        float x = p2[gm], y = p2[MM + gm], z = p2[2 * MM + gm];
        int pp = m >> 1, ln = m & 1;
        sXY[pp * 4 + ln] = x;     sXY[pp * 4 + 2 + ln] = y;
        sZW[pp * 4 + ln] = z;     sZW[pp * 4 + 2 + ln] = x * x + y * y + z * z;
    }
    __syncthreads();

    const int n = blockIdx.x * 128 + threadIdx.x;
    const float* p1 = pos1 + (size_t)b * 3 * NN;
    const float px = p1[n], py = p1[NN + n], pz = p1[2 * NN + n];
    const float n1 = px * px + py * py + pz * pz;
    const float mx2 = -2.0f * px, my2 = -2.0f * py, mz2 = -2.0f * pz;
    uint64_t QX, QY, QZ, NP;
    asm("mov.b64 %0, {%1, %2};" : "=l"(QX) : "f"(mx2), "f"(mx2));
    asm("mov.b64 %0, {%1, %2};" : "=l"(QY) : "f"(my2), "f"(my2));
    asm("mov.b64 %0, {%1, %2};" : "=l"(QZ) : "f"(mz2), "f"(mz2));
    asm("mov.b64 %0, {%1, %2};" : "=l"(NP) : "f"(n1), "f"(n1));

    float bestd[KK]; int besti[KK];
#pragma unroll
    for (int i = 0; i < KK; i++) { bestd[i] = 1e30f; besti[i] = mb; }
    float worst = 1e30f; int wslot = 0;

    auto ins = [&](float dv, int iv) {
        if (dv < worst) {
            bestd[wslot] = dv; besti[wslot] = iv;
            worst = bestd[0]; wslot = 0;
#pragma unroll
            for (int i = 1; i < KK; i++)
                if (bestd[i] > worst) { worst = bestd[i]; wslot = i; }
        }
    };

    uint32_t aXY = smem_u32(sXY), aZW = smem_u32(sZW);
    for (int g = 0; g < MCH / 4; g++) {
        uint64_t X0, Y0, X1, Y1, Z0, W0, Z1, W1, t0, t1;
        asm("ld.shared.v2.u64 {%0,%1}, [%2];"    : "=l"(X0), "=l"(Y0) : "r"(aXY));
        asm("ld.shared.v2.u64 {%0,%1}, [%2+16];" : "=l"(X1), "=l"(Y1) : "r"(aXY));
        asm("ld.shared.v2.u64 {%0,%1}, [%2];"    : "=l"(Z0), "=l"(W0) : "r"(aZW));
        asm("ld.shared.v2.u64 {%0,%1}, [%2+16];" : "=l"(Z1), "=l"(W1) : "r"(aZW));
        aXY += 32; aZW += 32;
        asm("add.rn.f32x2 %0, %1, %2;"     : "=l"(t0) : "l"(W0), "l"(NP));
        asm("fma.rn.f32x2 %0, %1, %2, %3;" : "=l"(t0) : "l"(QZ), "l"(Z0), "l"(t0));
        asm("fma.rn.f32x2 %0, %1, %2, %3;" : "=l"(t0) : "l"(QY), "l"(Y0), "l"(t0));
        asm("fma.rn.f32x2 %0, %1, %2, %3;" : "=l"(t0) : "l"(QX), "l"(X0), "l"(t0));
        asm("add.rn.f32x2 %0, %1, %2;"     : "=l"(t1) : "l"(W1), "l"(NP));
        asm("fma.rn.f32x2 %0, %1, %2, %3;" : "=l"(t1) : "l"(QZ), "l"(Z1), "l"(t1));
        asm("fma.rn.f32x2 %0, %1, %2, %3;" : "=l"(t1) : "l"(QY), "l"(Y1), "l"(t1));
        asm("fma.rn.f32x2 %0, %1, %2, %3;" : "=l"(t1) : "l"(QX), "l"(X1), "l"(t1));
        float d0, d1, d2, d3;
        asm("mov.b64 {%0,%1}, %2;" : "=f"(d0), "=f"(d1) : "l"(t0));
        asm("mov.b64 {%0,%1}, %2;" : "=f"(d2), "=f"(d3) : "l"(t1));
        float mn = fminf(fminf(d0, d1), fminf(d2, d3));
        if (mn < worst) {
            int ib = mb + g * 4;
            ins(d0, ib); ins(d1, ib + 1); ins(d2, ib + 2); ins(d3, ib + 3);
        }
    }
    size_t base = ((size_t)b * NN + n) * 16 + ms * 8;
#pragma unroll
    for (int i = 0; i < KK; i++) { g_cd[base + i] = bestd[i]; g_ci[base + i] = besti[i]; }
}

// ---------------------------------------------------------------------------
// mlp1 (wmma fp16): block = 128 cols (16 points x 8 nbrs); KNN merge fused in.
// ---------------------------------------------------------------------------
#define LDX 136
#define OFF_X 0
#define OFF_W 34816
#define OFF_SCR 69632
#define OFF_STAGE 79872
#define DSMEM1 88064

typedef wmma::fragment<wmma::matrix_a, 16, 16, 16, __half, wmma::row_major> frag_a;
typedef wmma::fragment<wmma::matrix_b, 16, 16, 16, __half, wmma::col_major> frag_bc;
typedef wmma::fragment<wmma::matrix_b, 16, 16, 16, __half, wmma::row_major> frag_br;
typedef wmma::fragment<wmma::accumulator, 16, 16, 16, float> frag_c;

__device__ __forceinline__ void load_w128(char* smp, const uint16_t* gh, int t) {
    const uint4* s = (const uint4*)gh;
    uint4* d = (uint4*)(smp + OFF_W);
    for (int i = t; i < 2048; i += 256) d[(i >> 4) * 17 + (i & 15)] = s[i];
}

__device__ __forceinline__ void gemm1(const char* smp, int mw, int nw, frag_c c[2][4]) {
    const __half* Wp = (const __half*)(smp + OFF_W);
    const __half* Xp = (const __half*)(smp + OFF_X);
#pragma unroll
    for (int mi = 0; mi < 2; mi++)
#pragma unroll
        for (int nt = 0; nt < 4; nt++) wmma::fill_fragment(c[mi][nt], 0.0f);
    for (int k0 = 0; k0 < 128; k0 += 16) {
        frag_a a0, a1;
        wmma::load_matrix_sync(a0, Wp + (mw * 32) * LDX + k0, LDX);
        wmma::load_matrix_sync(a1, Wp + (mw * 32 + 16) * LDX + k0, LDX);
#pragma unroll
        for (int nt = 0; nt < 4; nt++) {
            frag_bc bb;
            wmma::load_matrix_sync(bb, Xp + (nw * 64 + nt * 16) * LDX + k0, LDX);
            wmma::mma_sync(c[0][nt], a0, bb, c[0][nt]);
            wmma::mma_sync(c[1][nt], a1, bb, c[1][nt]);
        }
    }
}

__global__ __launch_bounds__(256, 2) void mlp1_wmma(
    const float* __restrict__ pos1, const float* __restrict__ pos2,
    const float* __restrict__ W0full, const float* __restrict__ S0,
    const float* __restrict__ B0, const float* __restrict__ B1,
    const float* __restrict__ B2) {
    extern __shared__ __align__(32) char smp[];
    __shared__ int sidx[128];
    __shared__ float sw0pos[3 * 128];

    const int t = threadIdx.x, wid = t >> 5, lid = t & 31;
    const int mw = wid & 3, nw = wid >> 2;
    const int b = blockIdx.y, n0 = blockIdx.x * 16;

    // fused KNN merge: top-8 of 16 candidates, (d, idx) lexicographic
    if (t < 16) {
        int n = n0 + t;
        size_t cb = ((size_t)b * NN + n) * 16;
        float cd[16]; int ci[16];
#pragma unroll
        for (int j = 0; j < 16; j++) { cd[j] = g_cd[cb + j]; ci[j] = g_ci[cb + j]; }
#pragma unroll
        for (int s = 0; s < 8; s++) {
            float dm = 1e38f; int im = 0x7fffffff, jm = 0;
#pragma unroll
            for (int j = 0; j < 16; j++) {
                bool bt = (cd[j] < dm) || (cd[j] == dm && ci[j] < im);
                if (bt) { dm = cd[j]; im = ci[j]; jm = j; }
            }
            sidx[t * 8 + s] = im;
#pragma unroll
            for (int j = 0; j < 16; j++) if (j == jm) cd[j] = 1e38f;
        }
    }
    for (int i = t; i < 384; i += 256) {
        int d = i >> 7, r = i & 127;
        sw0pos[i] = W0full[(size_t)r * C0 + 256 + d] * __ldg(&S0[r]);
    }
    __syncthreads();

    // ---- epilogue 0: gather y0 + pos correction, +b, ReLU -> X (fp16) ----
    {
        int col = t >> 1, half = t & 1;
        int m = sidx[col], n = n0 + (col >> 3);
        float pd0 = pos2[((size_t)b * 3 + 0) * MM + m] - pos1[((size_t)b * 3 + 0) * NN + n];
        float pd1 = pos2[((size_t)b * 3 + 1) * MM + m] - pos1[((size_t)b * 3 + 1) * NN + n];
        float pd2 = pos2[((size_t)b * 3 + 2) * MM + m] - pos1[((size_t)b * 3 + 2) * NN + n];
        const float4* yb = (const float4*)(g_y0 + ((size_t)b * MM + m) * 128 + half * 64);
        uint32_t* X32 = (uint32_t*)(smp + OFF_X);
#pragma unroll
        for (int i = 0; i < 16; i++) {
            float4 v = yb[i];
            float vv[4] = {v.x, v.y, v.z, v.w};
            uint16_t hh[4];
#pragma unroll
            for (int j = 0; j < 4; j++) {
                int r = half * 64 + i * 4 + j;
                float acc = vv[j] + pd0 * sw0pos[r] + pd1 * sw0pos[128 + r] + pd2 * sw0pos[256 + r];
                hh[j] = f2h(fmaxf(acc + __ldg(&B0[r]), 0.0f));
            }
            int e2 = (col * LDX + half * 64 + i * 4) >> 1;
            X32[e2]     = (uint32_t)hh[0] | ((uint32_t)hh[1] << 16);
            X32[e2 + 1] = (uint32_t)hh[2] | ((uint32_t)hh[3] << 16);
        }
    }
    load_w128(smp, g_w1h, t);
    __syncthreads();

    float* scr = (float*)(smp + OFF_SCR) + wid * 320;       // 16x20 fp32 warp-private
    uint16_t* stage = (uint16_t*)(smp + OFF_STAGE);          // [256][16] fp16
    uint16_t* Xb = (uint16_t*)(smp + OFF_X);

    // ---- layer 1: 128 -> 128 ----
    {
        frag_c c[2][4];
        gemm1(smp, mw, nw, c);
        __syncthreads();
#pragma unroll
        for (int mi = 0; mi < 2; mi++)
#pragma unroll
            for (int nt = 0; nt < 4; nt++) {
                wmma::store_matrix_sync(scr, c[mi][nt], 20, wmma::mem_row_major);
                __syncwarp();
                int r = lid & 15, ch2 = lid >> 4;
                int rowg = mw * 32 + mi * 16 + r;
                float bi = __ldg(&B1[rowg]);
#pragma unroll
                for (int j = 0; j < 8; j++) {
                    int colin = ch2 * 8 + j;
                    float y = fmaxf(scr[r * 20 + colin] + bi, 0.0f);
                    int colg = nw * 64 + nt * 16 + colin;
                    Xb[colg * LDX + rowg] = f2h(y);
                }
                __syncwarp();
            }
    }

    // ---- layer 2: 256 rows in two halves; maxpool over 8 nbrs -> stage ----
    for (int h = 0; h < 2; h++) {
        __syncthreads();
        load_w128(smp, g_w2h + h * 16384, t);
        __syncthreads();
        frag_c c[2][4];
        gemm1(smp, mw, nw, c);
        __syncthreads();
#pragma unroll
        for (int mi = 0; mi < 2; mi++)
#pragma unroll
            for (int nt = 0; nt < 4; nt++) {
                wmma::store_matrix_sync(scr, c[mi][nt], 20, wmma::mem_row_major);
                __syncwarp();
                int r = lid & 15, pt = lid >> 4;
                int rowg = mw * 32 + mi * 16 + r;
                int o = h * 128 + rowg;
                float bi = __ldg(&B2[o]);
                float mx = -1e30f;
#pragma unroll
                for (int j = 0; j < 8; j++)
                    mx = fmaxf(mx, scr[r * 20 + pt * 8 + j] + bi);
                stage[o * 16 + (nw * 8 + nt * 2 + pt)] = f2h(fmaxf(mx, 0.0f));
                __syncwarp();
            }
    }
    __syncthreads();
    if (t < 256) {
        const uint4* s = (const uint4*)(stage + t * 16);
        uint4* d = (uint4*)(&g_midh[((size_t)b * H2 + t) * NN + n0]);
        d[0] = s[0]; d[1] = s[1];
    }
}

// ---------------------------------------------------------------------------
// mlp2 (wmma fp16): out = relu(W20' @ concat(g_midh, f1) + b), 512 -> 256.
// feature1 converted fp32 -> fp16 inline while staging to smem.
// ---------------------------------------------------------------------------
#define DSMEM2 79872

__global__ __launch_bounds__(256, 2) void mlp2_wmma(
    const float* __restrict__ f1,
    const float* __restrict__ Bi, float* __restrict__ out) {
    extern __shared__ __align__(32) char smp[];
    const int t = threadIdx.x, wid = t >> 5, lid = t & 31;
    const int mw = wid & 3, nw = wid >> 2;
    const int b = blockIdx.z, m0b = blockIdx.y * 128, n0 = blockIdx.x * 128;

    uint16_t* Xc = (uint16_t*)(smp + OFF_X);
    uint16_t* Wc = (uint16_t*)(smp + OFF_W);
    float* scr = (float*)(smp + OFF_SCR) + wid * 320;

    frag_c c[2][4];
#pragma unroll
    for (int mi = 0; mi < 2; mi++)
#pragma unroll
        for (int nt = 0; nt < 4; nt++) wmma::fill_fragment(c[mi][nt], 0.0f);

    for (int ch = 0; ch < C2IN; ch += 128) {
        {
            uint4* d = (uint4*)Wc;
            for (int i = t; i < 2048; i += 256) {
                int row = i >> 4, q = i & 15;
                d[row * 17 + q] = ((const uint4*)(g_w20h + (size_t)(m0b + row) * 512 + ch))[q];
            }
        }
        {
            uint4* d = (uint4*)Xc;
            if (ch < 256) {
                const uint16_t* src = (const uint16_t*)&g_midh[((size_t)b * H2 + ch) * NN + n0];
                for (int i = t; i < 2048; i += 256) {
                    int row = i >> 4, q = i & 15;
                    d[row * 17 + q] = ((const uint4*)(src + (size_t)row * NN))[q];
                }
            } else {
                const float* srcf = f1 + ((size_t)b * F1C + (ch - 256)) * NN + n0;
                for (int i = t; i < 2048; i += 256) {
                    int row = i >> 4, q = i & 15;
                    const float4* s4 = (const float4*)(srcf + (size_t)row * NN);
                    float4 a = s4[q * 2], c2 = s4[q * 2 + 1];
                    uint4 v;
                    v.x = (uint32_t)f2h(a.x)  | ((uint32_t)f2h(a.y)  << 16);
                    v.y = (uint32_t)f2h(a.z)  | ((uint32_t)f2h(a.w)  << 16);
                    v.z = (uint32_t)f2h(c2.x) | ((uint32_t)f2h(c2.y) << 16);
                    v.w = (uint32_t)f2h(c2.z) | ((uint32_t)f2h(c2.w) << 16);
                    d[row * 17 + q] = v;
                }
            }
        }
        __syncthreads();
        const __half* Wp = (const __half*)Wc;
        const __half* Xp = (const __half*)Xc;
        for (int k0 = 0; k0 < 128; k0 += 16) {
            frag_a a0, a1;
            wmma::load_matrix_sync(a0, Wp + (mw * 32) * LDX + k0, LDX);
            wmma::load_matrix_sync(a1, Wp + (mw * 32 + 16) * LDX + k0, LDX);
#pragma unroll
            for (int nt = 0; nt < 4; nt++) {
                frag_br bb;
                wmma::load_matrix_sync(bb, Xp + k0 * LDX + (nw * 64 + nt * 16), LDX);
                wmma::mma_sync(c[0][nt], a0, bb, c[0][nt]);
                wmma::mma_sync(c[1][nt], a1, bb, c[1][nt]);
            }
        }
        __syncthreads();
    }

#pragma unroll
    for (int mi = 0; mi < 2; mi++)
#pragma unroll
        for (int nt = 0; nt < 4; nt++) {
            wmma::store_matrix_sync(scr, c[mi][nt], 20, wmma::mem_row_major);
            __syncwarp();
            int colin = lid & 15, rh = lid >> 4;
            int o = m0b + mw * 32 + mi * 16;
            int colg = n0 + nw * 64 + nt * 16 + colin;
#pragma unroll
            for (int j = 0; j < 8; j++) {
                int r = rh * 8 + j;
                float y = fmaxf(scr[r * 20 + colin] + __ldg(&Bi[o + r]), 0.0f);
                out[((size_t)b * H2 + o + r) * NN + colg] = y;
            }
            __syncwarp();
        }
}

// ---------------------------------------------------------------------------
extern "C" void kernel_launch(void* const* d_in, const int* in_sizes, int n_in,
                              void* d_out, int out_size) {
    const float* pos1     = (const float*)d_in[0];
    const float* pos2     = (const float*)d_in[1];
    const float* feature1 = (const float*)d_in[2];
    const float* feature2 = (const float*)d_in[3];
    const float* w1_0 = (const float*)d_in[4];
    const float* s1_0 = (const float*)d_in[5];
    const float* b1_0 = (const float*)d_in[6];
    const float* w1_1 = (const float*)d_in[7];
    const float* s1_1 = (const float*)d_in[8];
    const float* b1_1 = (const float*)d_in[9];
    const float* w1_2 = (const float*)d_in[10];
    const float* s1_2 = (const float*)d_in[11];
    const float* b1_2 = (const float*)d_in[12];
    const float* w2_0 = (const float*)d_in[13];
    const float* s2_0 = (const float*)d_in[14];
    const float* b2_0 = (const float*)d_in[15];
    float* out = (float*)d_out;

    static int attr_done = 0;
    if (!attr_done) {
        cudaFuncSetAttribute(mlp1_wmma, cudaFuncAttributeMaxDynamicSharedMemorySize, DSMEM1);
        cudaFuncSetAttribute(mlp2_wmma, cudaFuncAttributeMaxDynamicSharedMemorySize, DSMEM2);
        attr_done = 1;
    }

    prep_kernel<<<704, 256>>>(w1_1, s1_1, w1_2, s1_2, w2_0, s2_0);
    y0_kernel<<<dim3(MM / 32, BB), 128>>>(w1_0, s1_0, feature2);
    knn_scan<<<dim3(NN / 128, MS, BB), 128>>>(pos1, pos2);
    mlp1_wmma<<<dim3(NN / 16, BB), 256, DSMEM1>>>(pos1, pos2, w1_0, s1_0,
                                                  b1_0, b1_1, b1_2);
    mlp2_wmma<<<dim3(NN / 128, 2, BB), 256, DSMEM2>>>(feature1, b2_0, out);
}

// round 7
// speedup vs baseline: 5.7014x; 1.0348x over previous
#include <cuda_runtime.h>
#include <cuda_fp16.h>
#include <mma.h>
#include <cstdint>

using namespace nvcuda;

#define BB 4
#define NN 8192
#define MM 2048
#define KK 8
#define F1C 256
#define F2C 256
#define C0 259
#define H2 256
#define C2IN 512
#define MS 2
#define MCH (MM / MS)

// ---------------- scratch (__device__ globals) ----------------
__device__ float g_y0[(size_t)BB * MM * 128];                      // s0 * (W0_feat @ feature2)
__device__ __half g_midh[(size_t)BB * H2 * NN];                    // mlp1 output (fp16)
__device__ __align__(16) uint16_t g_w1h[128 * 128];
__device__ __align__(16) uint16_t g_w2h[256 * 128];
__device__ __align__(16) uint16_t g_w20h[256 * 512];
__device__ float g_cd[(size_t)BB * NN * 16];
__device__ int   g_ci[(size_t)BB * NN * 16];

__device__ __forceinline__ uint16_t f2h(float x) {
    return __half_as_ushort(__float2half_rn(x));
}
__device__ __forceinline__ uint32_t smem_u32(const void* p) {
    uint32_t a;
    asm("{ .reg .u64 t; cvta.to.shared.u64 t, %1; cvt.u32.u64 %0, t; }" : "=r"(a) : "l"(p));
    return a;
}
__device__ __forceinline__ uint32_t packh2(float lo, float hi) {
    return (uint32_t)f2h(lo) | ((uint32_t)f2h(hi) << 16);
}

// ---------------- mma.sync / ldmatrix primitives ----------------
__device__ __forceinline__ void ldsm4(uint32_t r[4], uint32_t addr) {
    asm volatile("ldmatrix.sync.aligned.m8n8.x4.shared.b16 {%0,%1,%2,%3}, [%4];"
                 : "=r"(r[0]), "=r"(r[1]), "=r"(r[2]), "=r"(r[3]) : "r"(addr));
}
__device__ __forceinline__ void ldsm4t(uint32_t r[4], uint32_t addr) {
    asm volatile("ldmatrix.sync.aligned.m8n8.x4.trans.shared.b16 {%0,%1,%2,%3}, [%4];"
                 : "=r"(r[0]), "=r"(r[1]), "=r"(r[2]), "=r"(r[3]) : "r"(addr));
}
__device__ __forceinline__ void mma16816(float c[4], const uint32_t a[4], const uint32_t* b) {
    asm volatile("mma.sync.aligned.m16n8k16.row.col.f32.f16.f16.f32 "
                 "{%0,%1,%2,%3}, {%4,%5,%6,%7}, {%8,%9}, {%0,%1,%2,%3};"
                 : "+f"(c[0]), "+f"(c[1]), "+f"(c[2]), "+f"(c[3])
                 : "r"(a[0]), "r"(a[1]), "r"(a[2]), "r"(a[3]), "r"(b[0]), "r"(b[1]));
}

// ---------------------------------------------------------------------------
// prep: weights -> fp16 with BN scale folded in (W' = diag(s) W)
// ---------------------------------------------------------------------------
__global__ void prep_kernel(const float* __restrict__ W1, const float* __restrict__ S1,
                            const float* __restrict__ W2, const float* __restrict__ S2,
                            const float* __restrict__ W20, const float* __restrict__ S20) {
    int t = blockIdx.x * blockDim.x + threadIdx.x;
    if (t < 16384) {
        g_w1h[t] = f2h(W1[t] * __ldg(&S1[t >> 7]));
    } else if (t < 49152) {
        int i = t - 16384;
        g_w2h[i] = f2h(W2[i] * __ldg(&S2[i >> 7]));
    } else if (t < 180224) {
        int i = t - 49152;
        g_w20h[i] = f2h(W20[i] * __ldg(&S20[i >> 9]));
    }
}

// ---------------------------------------------------------------------------
// y0: g_y0[b][m][r] = S0[r] * sum_c W0[r][c] * feature2[b][c][m]   (fp32)
// ---------------------------------------------------------------------------
__global__ __launch_bounds__(128) void y0_kernel(const float* __restrict__ W0,
                                                 const float* __restrict__ S0,
                                                 const float* __restrict__ f2) {
    __shared__ float tile[256][33];
    const int b = blockIdx.y, m0 = blockIdx.x * 32, t = threadIdx.x;
    for (int i = t; i < 256 * 32; i += 128) {
        int c = i >> 5, j = i & 31;
        tile[c][j] = f2[((size_t)b * F2C + c) * MM + m0 + j];
    }
    __syncthreads();
    const int r = t;
    float acc[32];
#pragma unroll
    for (int j = 0; j < 32; j++) acc[j] = 0.0f;
    const float* wrow = W0 + (size_t)r * C0;
#pragma unroll 4
    for (int c = 0; c < 256; c++) {
        float w = __ldg(&wrow[c]);
#pragma unroll
        for (int j = 0; j < 32; j++) acc[j] = fmaf(w, tile[c][j], acc[j]);
    }
    float s0 = __ldg(&S0[r]);
    for (int j = 0; j < 32; j++)
        g_y0[((size_t)b * MM + m0 + j) * 128 + r] = acc[j] * s0;
}

// ---------------------------------------------------------------------------
// KNN scan with packed f32x2 FMA
// ---------------------------------------------------------------------------
__global__ __launch_bounds__(128) void knn_scan(const float* __restrict__ pos1,
                                                const float* __restrict__ pos2) {
    __shared__ __align__(16) float sXY[MCH * 2];
    __shared__ __align__(16) float sZW[MCH * 2];
    const int b = blockIdx.z, ms = blockIdx.y, mb = ms * MCH;
    const float* p2 = pos2 + (size_t)b * 3 * MM;
    for (int m = threadIdx.x; m < MCH; m += 128) {
        int gm = mb + m;
        float x = p2[gm], y = p2[MM + gm], z = p2[2 * MM + gm];
        int pp = m >> 1, ln = m & 1;
        sXY[pp * 4 + ln] = x;     sXY[pp * 4 + 2 + ln] = y;
        sZW[pp * 4 + ln] = z;     sZW[pp * 4 + 2 + ln] = x * x + y * y + z * z;
    }
    __syncthreads();

    const int n = blockIdx.x * 128 + threadIdx.x;
    const float* p1 = pos1 + (size_t)b * 3 * NN;
    const float px = p1[n], py = p1[NN + n], pz = p1[2 * NN + n];
    const float n1 = px * px + py * py + pz * pz;
    const float mx2 = -2.0f * px, my2 = -2.0f * py, mz2 = -2.0f * pz;
    uint64_t QX, QY, QZ, NP;
    asm("mov.b64 %0, {%1, %2};" : "=l"(QX) : "f"(mx2), "f"(mx2));
    asm("mov.b64 %0, {%1, %2};" : "=l"(QY) : "f"(my2), "f"(my2));
    asm("mov.b64 %0, {%1, %2};" : "=l"(QZ) : "f"(mz2), "f"(mz2));
    asm("mov.b64 %0, {%1, %2};" : "=l"(NP) : "f"(n1), "f"(n1));

    float bestd[KK]; int besti[KK];
#pragma unroll
    for (int i = 0; i < KK; i++) { bestd[i] = 1e30f; besti[i] = mb; }
    float worst = 1e30f; int wslot = 0;

    auto ins = [&](float dv, int iv) {
        if (dv < worst) {
            bestd[wslot] = dv; besti[wslot] = iv;
            worst = bestd[0]; wslot = 0;
#pragma unroll
            for (int i = 1; i < KK; i++)
                if (bestd[i] > worst) { worst = bestd[i]; wslot = i; }
        }
    };

    uint32_t aXY = smem_u32(sXY), aZW = smem_u32(sZW);
    for (int g = 0; g < MCH / 4; g++) {
        uint64_t X0, Y0, X1, Y1, Z0, W0, Z1, W1, t0, t1;
        asm("ld.shared.v2.u64 {%0,%1}, [%2];"    : "=l"(X0), "=l"(Y0) : "r"(aXY));
        asm("ld.shared.v2.u64 {%0,%1}, [%2+16];" : "=l"(X1), "=l"(Y1) : "r"(aXY));
        asm("ld.shared.v2.u64 {%0,%1}, [%2];"    : "=l"(Z0), "=l"(W0) : "r"(aZW));
        asm("ld.shared.v2.u64 {%0,%1}, [%2+16];" : "=l"(Z1), "=l"(W1) : "r"(aZW));
        aXY += 32; aZW += 32;
        asm("add.rn.f32x2 %0, %1, %2;"     : "=l"(t0) : "l"(W0), "l"(NP));
        asm("fma.rn.f32x2 %0, %1, %2, %3;" : "=l"(t0) : "l"(QZ), "l"(Z0), "l"(t0));
        asm("fma.rn.f32x2 %0, %1, %2, %3;" : "=l"(t0) : "l"(QY), "l"(Y0), "l"(t0));
        asm("fma.rn.f32x2 %0, %1, %2, %3;" : "=l"(t0) : "l"(QX), "l"(X0), "l"(t0));
        asm("add.rn.f32x2 %0, %1, %2;"     : "=l"(t1) : "l"(W1), "l"(NP));
        asm("fma.rn.f32x2 %0, %1, %2, %3;" : "=l"(t1) : "l"(QZ), "l"(Z1), "l"(t1));
        asm("fma.rn.f32x2 %0, %1, %2, %3;" : "=l"(t1) : "l"(QY), "l"(Y1), "l"(t1));
        asm("fma.rn.f32x2 %0, %1, %2, %3;" : "=l"(t1) : "l"(QX), "l"(X1), "l"(t1));
        float d0, d1, d2, d3;
        asm("mov.b64 {%0,%1}, %2;" : "=f"(d0), "=f"(d1) : "l"(t0));
        asm("mov.b64 {%0,%1}, %2;" : "=f"(d2), "=f"(d3) : "l"(t1));
        float mn = fminf(fminf(d0, d1), fminf(d2, d3));
        if (mn < worst) {
            int ib = mb + g * 4;
            ins(d0, ib); ins(d1, ib + 1); ins(d2, ib + 2); ins(d3, ib + 3);
        }
    }
    size_t base = ((size_t)b * NN + n) * 16 + ms * 8;
#pragma unroll
    for (int i = 0; i < KK; i++) { g_cd[base + i] = bestd[i]; g_ci[base + i] = besti[i]; }
}

// ---------------------------------------------------------------------------
// mlp1 via raw mma.sync m16n8k16: block = 128 cols (16 points x 8 nbrs).
// X in smem row-major [k][n] (LD1=136), W row-major [m][k] (LD1=136).
// Register epilogues (no scratch roundtrip).
// ---------------------------------------------------------------------------
#define LD1 136
#define X1OFF 0
#define W1OFF 34816
#define STGOFF 69632
#define DSMEM1 77824

__device__ __forceinline__ void load_w1(char* smp, const uint16_t* gh, int t) {
    const uint4* s = (const uint4*)gh;
    uint4* d = (uint4*)(smp + W1OFF);
    for (int i = t; i < 2048; i += 256) d[(i >> 4) * 17 + (i & 15)] = s[i];
}

// warp computes rows [mw*32, +32), cols [nw*64, +64); accum c[2][8][4]
__device__ __forceinline__ void gemm_ms(uint32_t xu, uint32_t wu, int mw, int nw,
                                        int lid, float c[2][8][4]) {
#pragma unroll
    for (int mi = 0; mi < 2; mi++)
#pragma unroll
        for (int nt = 0; nt < 8; nt++)
#pragma unroll
            for (int q = 0; q < 4; q++) c[mi][nt][q] = 0.0f;

    uint32_t aA0 = wu + (uint32_t)(((mw * 32 + (lid & 15)) * LD1 + (lid >> 4) * 8) * 2);
    uint32_t aA1 = aA0 + 16 * LD1 * 2;
    uint32_t aB  = xu + (uint32_t)(((lid & 15) * LD1 + nw * 64 + (lid >> 4) * 8) * 2);

#pragma unroll
    for (int kt = 0; kt < 8; kt++) {
        uint32_t A0[4], A1[4];
        ldsm4(A0, aA0 + kt * 32);
        ldsm4(A1, aA1 + kt * 32);
#pragma unroll
        for (int ng = 0; ng < 4; ng++) {
            uint32_t Bv[4];
            ldsm4t(Bv, aB + kt * 16 * LD1 * 2 + ng * 32);
            mma16816(c[0][2 * ng],     A0, Bv);
            mma16816(c[0][2 * ng + 1], A0, Bv + 2);
            mma16816(c[1][2 * ng],     A1, Bv);
            mma16816(c[1][2 * ng + 1], A1, Bv + 2);
        }
    }
}

__global__ __launch_bounds__(256, 2) void mlp1_mma(
    const float* __restrict__ pos1, const float* __restrict__ pos2,
    const float* __restrict__ W0full, const float* __restrict__ S0,
    const float* __restrict__ B0, const float* __restrict__ B1,
    const float* __restrict__ B2) {
    extern __shared__ __align__(32) char smp[];
    __shared__ int sidx[128];
    __shared__ float sw0pos[3 * 128];
    __shared__ float sB0[128], sB1[128], sB2[256];

    const int t = threadIdx.x, wid = t >> 5, lid = t & 31;
    const int mw = wid & 3, nw = wid >> 2;
    const int b = blockIdx.y, n0 = blockIdx.x * 16;

    const uint32_t xu = smem_u32(smp + X1OFF);
    const uint32_t wu = smem_u32(smp + W1OFF);
    uint16_t* stage = (uint16_t*)(smp + STGOFF);

    // fused KNN merge: top-8 of 16 candidates, (d, idx) lexicographic
    if (t < 16) {
        int n = n0 + t;
        size_t cb = ((size_t)b * NN + n) * 16;
        float cd[16]; int ci[16];
#pragma unroll
        for (int j = 0; j < 16; j++) { cd[j] = g_cd[cb + j]; ci[j] = g_ci[cb + j]; }
#pragma unroll
        for (int s = 0; s < 8; s++) {
            float dm = 1e38f; int im = 0x7fffffff, jm = 0;
#pragma unroll
            for (int j = 0; j < 16; j++) {
                bool bt = (cd[j] < dm) || (cd[j] == dm && ci[j] < im);
                if (bt) { dm = cd[j]; im = ci[j]; jm = j; }
            }
            sidx[t * 8 + s] = im;
#pragma unroll
            for (int j = 0; j < 16; j++) if (j == jm) cd[j] = 1e38f;
        }
    }
    for (int i = t; i < 384; i += 256) {
        int d = i >> 7, r = i & 127;
        sw0pos[i] = W0full[(size_t)r * C0 + 256 + d] * __ldg(&S0[r]);
    }
    if (t < 128) { sB0[t] = B0[t]; sB1[t] = B1[t]; }
    for (int i = t; i < 256; i += 256) sB2[i] = B2[i];
    __syncthreads();

    // ---- epilogue 0: gather y0 + pos correction, +b, ReLU -> X0 [k][n] ----
    {
        int c2 = t & 63, qh = t >> 6;            // col pair (2 nbrs), k-quarter
        int ca = 2 * c2;
        int ma = sidx[ca], mb2 = sidx[ca + 1];
        int n = n0 + (c2 >> 2);
        float pa0 = pos2[((size_t)b * 3 + 0) * MM + ma]  - pos1[((size_t)b * 3 + 0) * NN + n];
        float pa1 = pos2[((size_t)b * 3 + 1) * MM + ma]  - pos1[((size_t)b * 3 + 1) * NN + n];
        float pa2 = pos2[((size_t)b * 3 + 2) * MM + ma]  - pos1[((size_t)b * 3 + 2) * NN + n];
        float pb0 = pos2[((size_t)b * 3 + 0) * MM + mb2] - pos1[((size_t)b * 3 + 0) * NN + n];
        float pb1 = pos2[((size_t)b * 3 + 1) * MM + mb2] - pos1[((size_t)b * 3 + 1) * NN + n];
        float pb2 = pos2[((size_t)b * 3 + 2) * MM + mb2] - pos1[((size_t)b * 3 + 2) * NN + n];
        const float4* ya = (const float4*)(g_y0 + ((size_t)b * MM + ma)  * 128 + 32 * qh);
        const float4* yb = (const float4*)(g_y0 + ((size_t)b * MM + mb2) * 128 + 32 * qh);
        uint32_t* X32 = (uint32_t*)(smp + X1OFF);
#pragma unroll
        for (int i = 0; i < 8; i++) {
            float4 va = ya[i], vb = yb[i];
            float aa[4] = {va.x, va.y, va.z, va.w};
            float bb[4] = {vb.x, vb.y, vb.z, vb.w};
#pragma unroll
            for (int j = 0; j < 4; j++) {
                int r = 32 * qh + i * 4 + j;
                float w0 = sw0pos[r], w1 = sw0pos[128 + r], w2 = sw0pos[256 + r];
                float fa = fmaxf(aa[j] + pa0 * w0 + pa1 * w1 + pa2 * w2 + sB0[r], 0.0f);
                float fb = fmaxf(bb[j] + pb0 * w0 + pb1 * w1 + pb2 * w2 + sB0[r], 0.0f);
                X32[r * (LD1 / 2) + c2] = packh2(fa, fb);
            }
        }
    }
    load_w1(smp, g_w1h, t);
    __syncthreads();

    float c[2][8][4];

    // ---- layer 1: 128 -> 128, register epilogue -> X1 in place ----
    gemm_ms(xu, wu, mw, nw, lid, c);
    __syncthreads();
    {
        uint32_t* X32 = (uint32_t*)(smp + X1OFF);
#pragma unroll
        for (int mi = 0; mi < 2; mi++) {
            int r0 = mw * 32 + mi * 16 + (lid >> 2), r1 = r0 + 8;
            float b0 = sB1[r0], b1 = sB1[r1];
#pragma unroll
            for (int nt = 0; nt < 8; nt++) {
                int col = nw * 64 + nt * 8 + (lid & 3) * 2;
                X32[(r0 * LD1 + col) >> 1] =
                    packh2(fmaxf(c[mi][nt][0] + b0, 0.0f), fmaxf(c[mi][nt][1] + b0, 0.0f));
                X32[(r1 * LD1 + col) >> 1] =
                    packh2(fmaxf(c[mi][nt][2] + b1, 0.0f), fmaxf(c[mi][nt][3] + b1, 0.0f));
            }
        }
    }
    load_w1(smp, g_w2h, t);
    __syncthreads();

    // ---- layer 2 (two 128-row halves): maxpool over 8 nbrs -> stage ----
#pragma unroll 1
    for (int h = 0; h < 2; h++) {
        gemm_ms(xu, wu, mw, nw, lid, c);
        __syncthreads();                                  // W reads done before reload
#pragma unroll
        for (int mi = 0; mi < 2; mi++) {
            int r0 = mw * 32 + mi * 16 + (lid >> 2);
            int o0 = h * 128 + r0, o1 = o0 + 8;
#pragma unroll
            for (int nt = 0; nt < 8; nt++) {
                int p = nw * 8 + nt;
                float m0 = fmaxf(c[mi][nt][0], c[mi][nt][1]);
                float m1 = fmaxf(c[mi][nt][2], c[mi][nt][3]);
                m0 = fmaxf(m0, __shfl_xor_sync(0xffffffffu, m0, 1));
                m0 = fmaxf(m0, __shfl_xor_sync(0xffffffffu, m0, 2));
                m1 = fmaxf(m1, __shfl_xor_sync(0xffffffffu, m1, 1));
                m1 = fmaxf(m1, __shfl_xor_sync(0xffffffffu, m1, 2));
                if ((lid & 3) == 0) {
                    stage[o0 * 16 + p] = f2h(fmaxf(m0 + sB2[o0], 0.0f));
                    stage[o1 * 16 + p] = f2h(fmaxf(m1 + sB2[o1], 0.0f));
                }
            }
        }
        if (h == 0) {
            load_w1(smp, g_w2h + 16384, t);
            __syncthreads();
        }
    }
    __syncthreads();
    {
        const uint4* s = (const uint4*)(stage + t * 16);
        uint4* d = (uint4*)(&g_midh[((size_t)b * H2 + t) * NN + n0]);
        d[0] = s[0]; d[1] = s[1];
    }
}

// ---------------------------------------------------------------------------
// mlp2 (wmma fp16): out = relu(W20' @ concat(g_midh, f1) + b), 512 -> 256.
// ---------------------------------------------------------------------------
#define LDX 136
#define OFF_X 0
#define OFF_W 34816
#define OFF_SCR 69632
#define DSMEM2 79872

typedef wmma::fragment<wmma::matrix_a, 16, 16, 16, __half, wmma::row_major> frag_a;
typedef wmma::fragment<wmma::matrix_b, 16, 16, 16, __half, wmma::row_major> frag_br;
typedef wmma::fragment<wmma::accumulator, 16, 16, 16, float> frag_c;

__global__ __launch_bounds__(256, 2) void mlp2_wmma(
    const float* __restrict__ f1,
    const float* __restrict__ Bi, float* __restrict__ out) {
    extern __shared__ __align__(32) char smp[];
    const int t = threadIdx.x, wid = t >> 5, lid = t & 31;
    const int mw = wid & 3, nw = wid >> 2;
    const int b = blockIdx.z, m0b = blockIdx.y * 128, n0 = blockIdx.x * 128;

    uint16_t* Xc = (uint16_t*)(smp + OFF_X);
    uint16_t* Wc = (uint16_t*)(smp + OFF_W);
    float* scr = (float*)(smp + OFF_SCR) + wid * 320;

    frag_c c[2][4];
#pragma unroll
    for (int mi = 0; mi < 2; mi++)
#pragma unroll
        for (int nt = 0; nt < 4; nt++) wmma::fill_fragment(c[mi][nt], 0.0f);

    for (int ch = 0; ch < C2IN; ch += 128) {
        {
            uint4* d = (uint4*)Wc;
            for (int i = t; i < 2048; i += 256) {
                int row = i >> 4, q = i & 15;
                d[row * 17 + q] = ((const uint4*)(g_w20h + (size_t)(m0b + row) * 512 + ch))[q];
            }
        }
        {
            uint4* d = (uint4*)Xc;
            if (ch < 256) {
                const uint16_t* src = (const uint16_t*)&g_midh[((size_t)b * H2 + ch) * NN + n0];
                for (int i = t; i < 2048; i += 256) {
                    int row = i >> 4, q = i & 15;
                    d[row * 17 + q] = ((const uint4*)(src + (size_t)row * NN))[q];
                }
            } else {
                const float* srcf = f1 + ((size_t)b * F1C + (ch - 256)) * NN + n0;
                for (int i = t; i < 2048; i += 256) {
                    int row = i >> 4, q = i & 15;
                    const float4* s4 = (const float4*)(srcf + (size_t)row * NN);
                    float4 a = s4[q * 2], c2 = s4[q * 2 + 1];
                    uint4 v;
                    v.x = packh2(a.x, a.y);  v.y = packh2(a.z, a.w);
                    v.z = packh2(c2.x, c2.y); v.w = packh2(c2.z, c2.w);
                    d[row * 17 + q] = v;
                }
            }
        }
        __syncthreads();
        const __half* Wp = (const __half*)Wc;
        const __half* Xp = (const __half*)Xc;
        for (int k0 = 0; k0 < 128; k0 += 16) {
            frag_a a0, a1;
            wmma::load_matrix_sync(a0, Wp + (mw * 32) * LDX + k0, LDX);
            wmma::load_matrix_sync(a1, Wp + (mw * 32 + 16) * LDX + k0, LDX);
#pragma unroll
            for (int nt = 0; nt < 4; nt++) {
                frag_br bb;
                wmma::load_matrix_sync(bb, Xp + k0 * LDX + (nw * 64 + nt * 16), LDX);
                wmma::mma_sync(c[0][nt], a0, bb, c[0][nt]);
                wmma::mma_sync(c[1][nt], a1, bb, c[1][nt]);
            }
        }
        __syncthreads();
    }

#pragma unroll
    for (int mi = 0; mi < 2; mi++)
#pragma unroll
        for (int nt = 0; nt < 4; nt++) {
            wmma::store_matrix_sync(scr, c[mi][nt], 20, wmma::mem_row_major);
            __syncwarp();
            int colin = lid & 15, rh = lid >> 4;
            int o = m0b + mw * 32 + mi * 16;
            int colg = n0 + nw * 64 + nt * 16 + colin;
#pragma unroll
            for (int j = 0; j < 8; j++) {
                int r = rh * 8 + j;
                float y = fmaxf(scr[r * 20 + colin] + __ldg(&Bi[o + r]), 0.0f);
                out[((size_t)b * H2 + o + r) * NN + colg] = y;
            }
            __syncwarp();
        }
}

// ---------------------------------------------------------------------------
extern "C" void kernel_launch(void* const* d_in, const int* in_sizes, int n_in,
                              void* d_out, int out_size) {
    const float* pos1     = (const float*)d_in[0];
    const float* pos2     = (const float*)d_in[1];
    const float* feature1 = (const float*)d_in[2];
    const float* feature2 = (const float*)d_in[3];
    const float* w1_0 = (const float*)d_in[4];
    const float* s1_0 = (const float*)d_in[5];
    const float* b1_0 = (const float*)d_in[6];
    const float* w1_1 = (const float*)d_in[7];
    const float* s1_1 = (const float*)d_in[8];
    const float* b1_1 = (const float*)d_in[9];
    const float* w1_2 = (const float*)d_in[10];
    const float* s1_2 = (const float*)d_in[11];
    const float* b1_2 = (const float*)d_in[12];
    const float* w2_0 = (const float*)d_in[13];
    const float* s2_0 = (const float*)d_in[14];
    const float* b2_0 = (const float*)d_in[15];
    float* out = (float*)d_out;

    static int attr_done = 0;
    if (!attr_done) {
        cudaFuncSetAttribute(mlp1_mma, cudaFuncAttributeMaxDynamicSharedMemorySize, DSMEM1);
        cudaFuncSetAttribute(mlp2_wmma, cudaFuncAttributeMaxDynamicSharedMemorySize, DSMEM2);
        attr_done = 1;
    }

    prep_kernel<<<704, 256>>>(w1_1, s1_1, w1_2, s1_2, w2_0, s2_0);
    y0_kernel<<<dim3(MM / 32, BB), 128>>>(w1_0, s1_0, feature2);
    knn_scan<<<dim3(NN / 128, MS, BB), 128>>>(pos1, pos2);
    mlp1_mma<<<dim3(NN / 16, BB), 256, DSMEM1>>>(pos1, pos2, w1_0, s1_0,
                                                 b1_0, b1_1, b1_2);
    mlp2_wmma<<<dim3(NN / 128, 2, BB), 256, DSMEM2>>>(feature1, b2_0, out);
}

// round 9
// speedup vs baseline: 5.9573x; 1.0449x over previous
#include <cuda_runtime.h>
#include <cuda_fp16.h>
#include <mma.h>
#include <cstdint>

using namespace nvcuda;

#define BB 4
#define NN 8192
#define MM 2048
#define KK 8
#define F1C 256
#define F2C 256
#define C0 259
#define H2 256
#define C2IN 512
#define MS 2
#define MCH (MM / MS)

// ---------------- scratch (__device__ globals) ----------------
__device__ float g_y0[(size_t)BB * MM * 128];                      // s0 * (W0_feat @ feature2)
__device__ __half g_midh[(size_t)BB * H2 * NN];                    // mlp1 output (fp16)
__device__ __align__(16) uint16_t g_w1h[128 * 128];
__device__ __align__(16) uint16_t g_w2h[256 * 128];
__device__ __align__(16) uint16_t g_w20h[256 * 512];
__device__ float g_cd[(size_t)BB * NN * 16];
__device__ int   g_ci[(size_t)BB * NN * 16];

__device__ __forceinline__ uint16_t f2h(float x) {
    return __half_as_ushort(__float2half_rn(x));
}
__device__ __forceinline__ uint32_t smem_u32(const void* p) {
    uint32_t a;
    asm("{ .reg .u64 t; cvta.to.shared.u64 t, %1; cvt.u32.u64 %0, t; }" : "=r"(a) : "l"(p));
    return a;
}
__device__ __forceinline__ uint32_t packh2(float lo, float hi) {
    return (uint32_t)f2h(lo) | ((uint32_t)f2h(hi) << 16);
}

// ---------------- mma.sync / ldmatrix / cp.async primitives ----------------
__device__ __forceinline__ void ldsm4(uint32_t r[4], uint32_t addr) {
    asm volatile("ldmatrix.sync.aligned.m8n8.x4.shared.b16 {%0,%1,%2,%3}, [%4];"
                 : "=r"(r[0]), "=r"(r[1]), "=r"(r[2]), "=r"(r[3]) : "r"(addr));
}
__device__ __forceinline__ void ldsm4t(uint32_t r[4], uint32_t addr) {
    asm volatile("ldmatrix.sync.aligned.m8n8.x4.trans.shared.b16 {%0,%1,%2,%3}, [%4];"
                 : "=r"(r[0]), "=r"(r[1]), "=r"(r[2]), "=r"(r[3]) : "r"(addr));
}
__device__ __forceinline__ void mma16816(float c[4], const uint32_t a[4], const uint32_t* b) {
    asm volatile("mma.sync.aligned.m16n8k16.row.col.f32.f16.f16.f32 "
                 "{%0,%1,%2,%3}, {%4,%5,%6,%7}, {%8,%9}, {%0,%1,%2,%3};"
                 : "+f"(c[0]), "+f"(c[1]), "+f"(c[2]), "+f"(c[3])
                 : "r"(a[0]), "r"(a[1]), "r"(a[2]), "r"(a[3]), "r"(b[0]), "r"(b[1]));
}
#define CP16(dst, src) asm volatile("cp.async.cg.shared.global [%0], [%1], 16;" :: "r"(dst), "l"(src))
#define CP_COMMIT()    asm volatile("cp.async.commit_group;")
#define CP_WAIT(n)     asm volatile("cp.async.wait_group %0;" :: "n"(n))

// ---------------------------------------------------------------------------
// prep: weights -> fp16 with BN scale folded in (W' = diag(s) W)
// ---------------------------------------------------------------------------
__global__ void prep_kernel(const float* __restrict__ W1, const float* __restrict__ S1,
                            const float* __restrict__ W2, const float* __restrict__ S2,
                            const float* __restrict__ W20, const float* __restrict__ S20) {
    int t = blockIdx.x * blockDim.x + threadIdx.x;
    if (t < 16384) {
        g_w1h[t] = f2h(W1[t] * __ldg(&S1[t >> 7]));
    } else if (t < 49152) {
        int i = t - 16384;
        g_w2h[i] = f2h(W2[i] * __ldg(&S2[i >> 7]));
    } else if (t < 180224) {
        int i = t - 49152;
        g_w20h[i] = f2h(W20[i] * __ldg(&S20[i >> 9]));
    }
}

// ---------------------------------------------------------------------------
// y0: g_y0[b][m][r] = S0[r] * sum_c W0[r][c] * feature2[b][c][m]   (fp32)
// ---------------------------------------------------------------------------
__global__ __launch_bounds__(128) void y0_kernel(const float* __restrict__ W0,
                                                 const float* __restrict__ S0,
                                                 const float* __restrict__ f2) {
    __shared__ float tile[256][33];
    const int b = blockIdx.y, m0 = blockIdx.x * 32, t = threadIdx.x;
    for (int i = t; i < 256 * 32; i += 128) {
        int c = i >> 5, j = i & 31;
        tile[c][j] = f2[((size_t)b * F2C + c) * MM + m0 + j];
    }
    __syncthreads();
    const int r = t;
    float acc[32];
#pragma unroll
    for (int j = 0; j < 32; j++) acc[j] = 0.0f;
    const float* wrow = W0 + (size_t)r * C0;
#pragma unroll 4
    for (int c = 0; c < 256; c++) {
        float w = __ldg(&wrow[c]);
#pragma unroll
        for (int j = 0; j < 32; j++) acc[j] = fmaf(w, tile[c][j], acc[j]);
    }
    float s0 = __ldg(&S0[r]);
    for (int j = 0; j < 32; j++)
        g_y0[((size_t)b * MM + m0 + j) * 128 + r] = acc[j] * s0;
}

// ---------------------------------------------------------------------------
// KNN scan with packed f32x2 FMA
// ---------------------------------------------------------------------------
__global__ __launch_bounds__(128) void knn_scan(const float* __restrict__ pos1,
                                                const float* __restrict__ pos2) {
    __shared__ __align__(16) float sXY[MCH * 2];
    __shared__ __align__(16) float sZW[MCH * 2];
    const int b = blockIdx.z, ms = blockIdx.y, mb = ms * MCH;
    const float* p2 = pos2 + (size_t)b * 3 * MM;
    for (int m = threadIdx.x; m < MCH; m += 128) {
        int gm = mb + m;
        float x = p2[gm], y = p2[MM + gm], z = p2[2 * MM + gm];
        int pp = m >> 1, ln = m & 1;
        sXY[pp * 4 + ln] = x;     sXY[pp * 4 + 2 + ln] = y;
        sZW[pp * 4 + ln] = z;     sZW[pp * 4 + 2 + ln] = x * x + y * y + z * z;
    }
    __syncthreads();

    const int n = blockIdx.x * 128 + threadIdx.x;
    const float* p1 = pos1 + (size_t)b * 3 * NN;
    const float px = p1[n], py = p1[NN + n], pz = p1[2 * NN + n];
    const float n1 = px * px + py * py + pz * pz;
    const float mx2 = -2.0f * px, my2 = -2.0f * py, mz2 = -2.0f * pz;
    uint64_t QX, QY, QZ, NP;
    asm("mov.b64 %0, {%1, %2};" : "=l"(QX) : "f"(mx2), "f"(mx2));
    asm("mov.b64 %0, {%1, %2};" : "=l"(QY) : "f"(my2), "f"(my2));
    asm("mov.b64 %0, {%1, %2};" : "=l"(QZ) : "f"(mz2), "f"(mz2));
    asm("mov.b64 %0, {%1, %2};" : "=l"(NP) : "f"(n1), "f"(n1));

    float bestd[KK]; int besti[KK];
#pragma unroll
    for (int i = 0; i < KK; i++) { bestd[i] = 1e30f; besti[i] = mb; }
    float worst = 1e30f; int wslot = 0;

    auto ins = [&](float dv, int iv) {
        if (dv < worst) {
            bestd[wslot] = dv; besti[wslot] = iv;
            worst = bestd[0]; wslot = 0;
#pragma unroll
            for (int i = 1; i < KK; i++)
                if (bestd[i] > worst) { worst = bestd[i]; wslot = i; }
        }
    };

    uint32_t aXY = smem_u32(sXY), aZW = smem_u32(sZW);
    for (int g = 0; g < MCH / 4; g++) {
        uint64_t X0, Y0, X1, Y1, Z0, W0, Z1, W1, t0, t1;
        asm("ld.shared.v2.u64 {%0,%1}, [%2];"    : "=l"(X0), "=l"(Y0) : "r"(aXY));
        asm("ld.shared.v2.u64 {%0,%1}, [%2+16];" : "=l"(X1), "=l"(Y1) : "r"(aXY));
        asm("ld.shared.v2.u64 {%0,%1}, [%2];"    : "=l"(Z0), "=l"(W0) : "r"(aZW));
        asm("ld.shared.v2.u64 {%0,%1}, [%2+16];" : "=l"(Z1), "=l"(W1) : "r"(aZW));
        aXY += 32; aZW += 32;
        asm("add.rn.f32x2 %0, %1, %2;"     : "=l"(t0) : "l"(W0), "l"(NP));
        asm("fma.rn.f32x2 %0, %1, %2, %3;" : "=l"(t0) : "l"(QZ), "l"(Z0), "l"(t0));
        asm("fma.rn.f32x2 %0, %1, %2, %3;" : "=l"(t0) : "l"(QY), "l"(Y0), "l"(t0));
        asm("fma.rn.f32x2 %0, %1, %2, %3;" : "=l"(t0) : "l"(QX), "l"(X0), "l"(t0));
        asm("add.rn.f32x2 %0, %1, %2;"     : "=l"(t1) : "l"(W1), "l"(NP));
        asm("fma.rn.f32x2 %0, %1, %2, %3;" : "=l"(t1) : "l"(QZ), "l"(Z1), "l"(t1));
        asm("fma.rn.f32x2 %0, %1, %2, %3;" : "=l"(t1) : "l"(QY), "l"(Y1), "l"(t1));
        asm("fma.rn.f32x2 %0, %1, %2, %3;" : "=l"(t1) : "l"(QX), "l"(X1), "l"(t1));
        float d0, d1, d2, d3;
        asm("mov.b64 {%0,%1}, %2;" : "=f"(d0), "=f"(d1) : "l"(t0));
        asm("mov.b64 {%0,%1}, %2;" : "=f"(d2), "=f"(d3) : "l"(t1));
        float mn = fminf(fminf(d0, d1), fminf(d2, d3));
        if (mn < worst) {
            int ib = mb + g * 4;
            ins(d0, ib); ins(d1, ib + 1); ins(d2, ib + 2); ins(d3, ib + 3);
        }
    }
    size_t base = ((size_t)b * NN + n) * 16 + ms * 8;
#pragma unroll
    for (int i = 0; i < KK; i++) { g_cd[base + i] = bestd[i]; g_ci[base + i] = besti[i]; }
}

// ---------------------------------------------------------------------------
// mlp1 via raw mma.sync + cp.async pipelined weight loads.
// smem: X (34816) | W two slots (2x34816) | stage (8192, small arrays aliased)
// ---------------------------------------------------------------------------
#define LD1 136
#define X1OFF 0
#define W1OFF 34816
#define W2OFF 69632
#define STGOFF 104448
#define DSMEM1 112640

// cp.async a 128x128 fp16 weight matrix into padded layout at smem addr wdst
__device__ __forceinline__ void cpa_w(uint32_t wdst, const uint16_t* gh, int t) {
#pragma unroll
    for (int k = 0; k < 8; k++) {
        int i = t + k * 256;
        CP16(wdst + (uint32_t)(((i >> 4) * 17 + (i & 15)) * 16), (const char*)gh + i * 16);
    }
}

// warp computes rows [mw*32, +32), cols [nw*64, +64); accum c[2][8][4]
__device__ __forceinline__ void gemm_ms(uint32_t xu, uint32_t wu, int mw, int nw,
                                        int lid, float c[2][8][4]) {
#pragma unroll
    for (int mi = 0; mi < 2; mi++)
#pragma unroll
        for (int nt = 0; nt < 8; nt++)
#pragma unroll
            for (int q = 0; q < 4; q++) c[mi][nt][q] = 0.0f;

    uint32_t aA0 = wu + (uint32_t)(((mw * 32 + (lid & 15)) * LD1 + (lid >> 4) * 8) * 2);
    uint32_t aA1 = aA0 + 16 * LD1 * 2;
    uint32_t aB  = xu + (uint32_t)(((lid & 15) * LD1 + nw * 64 + (lid >> 4) * 8) * 2);

#pragma unroll
    for (int kt = 0; kt < 8; kt++) {
        uint32_t A0[4], A1[4];
        ldsm4(A0, aA0 + kt * 32);
        ldsm4(A1, aA1 + kt * 32);
#pragma unroll
        for (int ng = 0; ng < 4; ng++) {
            uint32_t Bv[4];
            ldsm4t(Bv, aB + kt * 16 * LD1 * 2 + ng * 32);
            mma16816(c[0][2 * ng],     A0, Bv);
            mma16816(c[0][2 * ng + 1], A0, Bv + 2);
            mma16816(c[1][2 * ng],     A1, Bv);
            mma16816(c[1][2 * ng + 1], A1, Bv + 2);
        }
    }
}

__global__ __launch_bounds__(256, 2) void mlp1_mma(
    const float* __restrict__ pos1, const float* __restrict__ pos2,
    const float* __restrict__ W0full, const float* __restrict__ S0,
    const float* __restrict__ B0, const float* __restrict__ B1,
    const float* __restrict__ B2) {
    extern __shared__ __align__(32) char smp[];

    const int t = threadIdx.x, wid = t >> 5, lid = t & 31;
    const int mw = wid & 3, nw = wid >> 2;
    const int b = blockIdx.y, n0 = blockIdx.x * 16;

    const uint32_t xu  = smem_u32(smp + X1OFF);
    const uint32_t wuA = smem_u32(smp + W1OFF);
    const uint32_t wuB = smem_u32(smp + W2OFF);
    uint16_t* stage = (uint16_t*)(smp + STGOFF);
    // small arrays aliased into stage region (consumed before any stage write)
    int*   sidx   = (int*)(smp + STGOFF);            // 512 B
    float* sw0pos = (float*)(smp + STGOFF + 512);    // 1536 B
    float* sB0    = (float*)(smp + STGOFF + 2048);   // 512 B
    float* sB1    = (float*)(smp + STGOFF + 2560);   // 512 B

    // kick off weight prefetch immediately (hidden under merge + epilogue0)
    cpa_w(wuA, g_w1h, t); CP_COMMIT();                 // group: W1
    cpa_w(wuB, g_w2h, t); CP_COMMIT();                 // group: W2 half0

    // fused KNN merge: top-8 of 16 candidates, (d, idx) lexicographic
    if (t < 16) {
        int n = n0 + t;
        size_t cb = ((size_t)b * NN + n) * 16;
        float cd[16]; int ci[16];
#pragma unroll
        for (int j = 0; j < 16; j++) { cd[j] = g_cd[cb + j]; ci[j] = g_ci[cb + j]; }
#pragma unroll
        for (int s = 0; s < 8; s++) {
            float dm = 1e38f; int im = 0x7fffffff, jm = 0;
#pragma unroll
            for (int j = 0; j < 16; j++) {
                bool bt = (cd[j] < dm) || (cd[j] == dm && ci[j] < im);
                if (bt) { dm = cd[j]; im = ci[j]; jm = j; }
            }
            sidx[t * 8 + s] = im;
#pragma unroll
            for (int j = 0; j < 16; j++) if (j == jm) cd[j] = 1e38f;
        }
    }
    for (int i = t; i < 384; i += 256) {
        int d = i >> 7, r = i & 127;
        sw0pos[i] = W0full[(size_t)r * C0 + 256 + d] * __ldg(&S0[r]);
    }
    if (t < 128) { sB0[t] = B0[t]; sB1[t] = B1[t]; }
    __syncthreads();

    // ---- epilogue 0: gather y0 + pos correction, +b, ReLU -> X0 [k][n] ----
    {
        int c2 = t & 63, qh = t >> 6;            // col pair (2 nbrs), k-quarter
        int ca = 2 * c2;
        int ma = sidx[ca], mb2 = sidx[ca + 1];
        int n = n0 + (c2 >> 2);
        float pa0 = pos2[((size_t)b * 3 + 0) * MM + ma]  - pos1[((size_t)b * 3 + 0) * NN + n];
        float pa1 = pos2[((size_t)b * 3 + 1) * MM + ma]  - pos1[((size_t)b * 3 + 1) * NN + n];
        float pa2 = pos2[((size_t)b * 3 + 2) * MM + ma]  - pos1[((size_t)b * 3 + 2) * NN + n];
        float pb0 = pos2[((size_t)b * 3 + 0) * MM + mb2] - pos1[((size_t)b * 3 + 0) * NN + n];
        float pb1 = pos2[((size_t)b * 3 + 1) * MM + mb2] - pos1[((size_t)b * 3 + 1) * NN + n];
        float pb2 = pos2[((size_t)b * 3 + 2) * MM + mb2] - pos1[((size_t)b * 3 + 2) * NN + n];
        const float4* ya = (const float4*)(g_y0 + ((size_t)b * MM + ma)  * 128 + 32 * qh);
        const float4* yb = (const float4*)(g_y0 + ((size_t)b * MM + mb2) * 128 + 32 * qh);
        uint32_t* X32 = (uint32_t*)(smp + X1OFF);
#pragma unroll
        for (int i = 0; i < 8; i++) {
            float4 va = ya[i], vb = yb[i];
            float aa[4] = {va.x, va.y, va.z, va.w};
            float bb[4] = {vb.x, vb.y, vb.z, vb.w};
#pragma unroll
            for (int j = 0; j < 4; j++) {
                int r = 32 * qh + i * 4 + j;
                float w0 = sw0pos[r], w1 = sw0pos[128 + r], w2 = sw0pos[256 + r];
                float fa = fmaxf(aa[j] + pa0 * w0 + pa1 * w1 + pa2 * w2 + sB0[r], 0.0f);
                float fb = fmaxf(bb[j] + pb0 * w0 + pb1 * w1 + pb2 * w2 + sB0[r], 0.0f);
                X32[r * (LD1 / 2) + c2] = packh2(fa, fb);
            }
        }
    }
    CP_WAIT(1);                                       // W1 in smem (W2h0 may pend)
    __syncthreads();

    float c[2][8][4];

    // ---- layer 1: 128 -> 128, pack epilogue in regs BEFORE barrier ----
    gemm_ms(xu, wuA, mw, nw, lid, c);
    uint32_t pk[2][8][2];
    {
#pragma unroll
        for (int mi = 0; mi < 2; mi++) {
            int r0 = mw * 32 + mi * 16 + (lid >> 2), r1 = r0 + 8;
            float b0 = sB1[r0], b1 = sB1[r1];
#pragma unroll
            for (int nt = 0; nt < 8; nt++) {
                pk[mi][nt][0] = packh2(fmaxf(c[mi][nt][0] + b0, 0.0f),
                                       fmaxf(c[mi][nt][1] + b0, 0.0f));
                pk[mi][nt][1] = packh2(fmaxf(c[mi][nt][2] + b1, 0.0f),
                                       fmaxf(c[mi][nt][3] + b1, 0.0f));
            }
        }
    }
    __syncthreads();                                  // all X0/W1 reads complete
    {
        uint32_t* X32 = (uint32_t*)(smp + X1OFF);
#pragma unroll
        for (int mi = 0; mi < 2; mi++) {
            int r0 = mw * 32 + mi * 16 + (lid >> 2), r1 = r0 + 8;
#pragma unroll
            for (int nt = 0; nt < 8; nt++) {
                int col = nw * 64 + nt * 8 + (lid & 3) * 2;
                X32[(r0 * LD1 + col) >> 1] = pk[mi][nt][0];
                X32[(r1 * LD1 + col) >> 1] = pk[mi][nt][1];
            }
        }
    }
    cpa_w(wuA, g_w2h + 16384, t); CP_COMMIT();        // W2 half1 -> slot A (safe: W1 reads done)
    CP_WAIT(1);                                       // W2h0 resident (h1 may pend)
    __syncthreads();                                  // X1 visible

    // ---- layer 2 half 0 (slot B) ----
    gemm_ms(xu, wuB, mw, nw, lid, c);
#pragma unroll
    for (int mi = 0; mi < 2; mi++) {
        int r0 = mw * 32 + mi * 16 + (lid >> 2);
        int o0 = r0, o1 = r0 + 8;
#pragma unroll
        for (int nt = 0; nt < 8; nt++) {
            int p = nw * 8 + nt;
            float m0 = fmaxf(c[mi][nt][0], c[mi][nt][1]);
            float m1 = fmaxf(c[mi][nt][2], c[mi][nt][3]);
            m0 = fmaxf(m0, __shfl_xor_sync(0xffffffffu, m0, 1));
            m0 = fmaxf(m0, __shfl_xor_sync(0xffffffffu, m0, 2));
            m1 = fmaxf(m1, __shfl_xor_sync(0xffffffffu, m1, 1));
            m1 = fmaxf(m1, __shfl_xor_sync(0xffffffffu, m1, 2));
            if ((lid & 3) == 0) {
                stage[o0 * 16 + p] = f2h(fmaxf(m0 + __ldg(&B2[o0]), 0.0f));
                stage[o1 * 16 + p] = f2h(fmaxf(m1 + __ldg(&B2[o1]), 0.0f));
            }
        }
    }
    CP_WAIT(0);                                       // W2h1 resident
    __syncthreads();

    // ---- layer 2 half 1 (slot A) ----
    gemm_ms(xu, wuA, mw, nw, lid, c);
#pragma unroll
    for (int mi = 0; mi < 2; mi++) {
        int r0 = mw * 32 + mi * 16 + (lid >> 2);
        int o0 = 128 + r0, o1 = o0 + 8;
#pragma unroll
        for (int nt = 0; nt < 8; nt++) {
            int p = nw * 8 + nt;
            float m0 = fmaxf(c[mi][nt][0], c[mi][nt][1]);
            float m1 = fmaxf(c[mi][nt][2], c[mi][nt][3]);
            m0 = fmaxf(m0, __shfl_xor_sync(0xffffffffu, m0, 1));
            m0 = fmaxf(m0, __shfl_xor_sync(0xffffffffu, m0, 2));
            m1 = fmaxf(m1, __shfl_xor_sync(0xffffffffu, m1, 1));
            m1 = fmaxf(m1, __shfl_xor_sync(0xffffffffu, m1, 2));
            if ((lid & 3) == 0) {
                stage[o0 * 16 + p] = f2h(fmaxf(m0 + __ldg(&B2[o0]), 0.0f));
                stage[o1 * 16 + p] = f2h(fmaxf(m1 + __ldg(&B2[o1]), 0.0f));
            }
        }
    }
    __syncthreads();
    {
        const uint4* s = (const uint4*)(stage + t * 16);
        uint4* d = (uint4*)(&g_midh[((size_t)b * H2 + t) * NN + n0]);
        d[0] = s[0]; d[1] = s[1];
    }
}

// ---------------------------------------------------------------------------
// mlp2 (wmma fp16): out = relu(W20' @ concat(g_midh, f1) + b), 512 -> 256.
// ---------------------------------------------------------------------------
#define LDX 136
#define OFF_X 0
#define OFF_W 34816
#define OFF_SCR 69632
#define DSMEM2 79872

typedef wmma::fragment<wmma::matrix_a, 16, 16, 16, __half, wmma::row_major> frag_a;
typedef wmma::fragment<wmma::matrix_b, 16, 16, 16, __half, wmma::row_major> frag_br;
typedef wmma::fragment<wmma::accumulator, 16, 16, 16, float> frag_c;

__global__ __launch_bounds__(256, 2) void mlp2_wmma(
    const float* __restrict__ f1,
    const float* __restrict__ Bi, float* __restrict__ out) {
    extern __shared__ __align__(32) char smp[];
    const int t = threadIdx.x, wid = t >> 5, lid = t & 31;
    const int mw = wid & 3, nw = wid >> 2;
    const int b = blockIdx.z, m0b = blockIdx.y * 128, n0 = blockIdx.x * 128;

    uint16_t* Xc = (uint16_t*)(smp + OFF_X);
    uint16_t* Wc = (uint16_t*)(smp + OFF_W);
    float* scr = (float*)(smp + OFF_SCR) + wid * 320;

    frag_c c[2][4];
#pragma unroll
    for (int mi = 0; mi < 2; mi++)
#pragma unroll
        for (int nt = 0; nt < 4; nt++) wmma::fill_fragment(c[mi][nt], 0.0f);

    for (int ch = 0; ch < C2IN; ch += 128) {
        {
            uint32_t wdst = smem_u32(Wc);
            for (int i = t; i < 2048; i += 256)
                CP16(wdst + (uint32_t)(((i >> 4) * 17 + (i & 15)) * 16),
                     (const char*)(g_w20h + (size_t)(m0b + (i >> 4)) * 512 + ch) + (i & 15) * 16);
        }
        {
            uint4* d = (uint4*)Xc;
            if (ch < 256) {
                uint32_t xdst = smem_u32(Xc);
                const char* src = (const char*)&g_midh[((size_t)b * H2 + ch) * NN + n0];
                for (int i = t; i < 2048; i += 256)
                    CP16(xdst + (uint32_t)(((i >> 4) * 17 + (i & 15)) * 16),
                         src + (size_t)(i >> 4) * NN * 2 + (i & 15) * 16);
            } else {
                const float* srcf = f1 + ((size_t)b * F1C + (ch - 256)) * NN + n0;
                for (int i = t; i < 2048; i += 256) {
                    int row = i >> 4, q = i & 15;
                    const float4* s4 = (const float4*)(srcf + (size_t)row * NN);
                    float4 a = s4[q * 2], c2 = s4[q * 2 + 1];
                    uint4 v;
                    v.x = packh2(a.x, a.y);  v.y = packh2(a.z, a.w);
                    v.z = packh2(c2.x, c2.y); v.w = packh2(c2.z, c2.w);
                    d[row * 17 + q] = v;
                }
            }
        }
        CP_COMMIT();                                  // FIX: commit before wait
        CP_WAIT(0);
        __syncthreads();
        const __half* Wp = (const __half*)Wc;
        const __half* Xp = (const __half*)Xc;
        for (int k0 = 0; k0 < 128; k0 += 16) {
            frag_a a0, a1;
            wmma::load_matrix_sync(a0, Wp + (mw * 32) * LDX + k0, LDX);
            wmma::load_matrix_sync(a1, Wp + (mw * 32 + 16) * LDX + k0, LDX);
#pragma unroll
            for (int nt = 0; nt < 4; nt++) {
                frag_br bb;
                wmma::load_matrix_sync(bb, Xp + k0 * LDX + (nw * 64 + nt * 16), LDX);
                wmma::mma_sync(c[0][nt], a0, bb, c[0][nt]);
                wmma::mma_sync(c[1][nt], a1, bb, c[1][nt]);
            }
        }
        __syncthreads();
    }

#pragma unroll
    for (int mi = 0; mi < 2; mi++)
#pragma unroll
        for (int nt = 0; nt < 4; nt++) {
            wmma::store_matrix_sync(scr, c[mi][nt], 20, wmma::mem_row_major);
            __syncwarp();
            int colin = lid & 15, rh = lid >> 4;
            int o = m0b + mw * 32 + mi * 16;
            int colg = n0 + nw * 64 + nt * 16 + colin;
#pragma unroll
            for (int j = 0; j < 8; j++) {
                int r = rh * 8 + j;
                float y = fmaxf(scr[r * 20 + colin] + __ldg(&Bi[o + r]), 0.0f);
                out[((size_t)b * H2 + o + r) * NN + colg] = y;
            }
            __syncwarp();
        }
}

// ---------------------------------------------------------------------------
extern "C" void kernel_launch(void* const* d_in, const int* in_sizes, int n_in,
                              void* d_out, int out_size) {
    const float* pos1     = (const float*)d_in[0];
    const float* pos2     = (const float*)d_in[1];
    const float* feature1 = (const float*)d_in[2];
    const float* feature2 = (const float*)d_in[3];
    const float* w1_0 = (const float*)d_in[4];
    const float* s1_0 = (const float*)d_in[5];
    const float* b1_0 = (const float*)d_in[6];
    const float* w1_1 = (const float*)d_in[7];
    const float* s1_1 = (const float*)d_in[8];
    const float* b1_1 = (const float*)d_in[9];
    const float* w1_2 = (const float*)d_in[10];
    const float* s1_2 = (const float*)d_in[11];
    const float* b1_2 = (const float*)d_in[12];
    const float* w2_0 = (const float*)d_in[13];
    const float* s2_0 = (const float*)d_in[14];
    const float* b2_0 = (const float*)d_in[15];
    float* out = (float*)d_out;

    static int attr_done = 0;
    if (!attr_done) {
        cudaFuncSetAttribute(mlp1_mma, cudaFuncAttributeMaxDynamicSharedMemorySize, DSMEM1);
        cudaFuncSetAttribute(mlp2_wmma, cudaFuncAttributeMaxDynamicSharedMemorySize, DSMEM2);
        attr_done = 1;
    }

    prep_kernel<<<704, 256>>>(w1_1, s1_1, w1_2, s1_2, w2_0, s2_0);
    y0_kernel<<<dim3(MM / 32, BB), 128>>>(w1_0, s1_0, feature2);
    knn_scan<<<dim3(NN / 128, MS, BB), 128>>>(pos1, pos2);
    mlp1_mma<<<dim3(NN / 16, BB), 256, DSMEM1>>>(pos1, pos2, w1_0, s1_0,
                                                 b1_0, b1_1, b1_2);
    mlp2_wmma<<<dim3(NN / 128, 2, BB), 256, DSMEM2>>>(feature1, b2_0, out);
}

// round 10
// speedup vs baseline: 7.1329x; 1.1973x over previous
#include <cuda_runtime.h>
#include <cuda_fp16.h>
#include <mma.h>
#include <cstdint>

using namespace nvcuda;

#define BB 4
#define NN 8192
#define MM 2048
#define KK 8
#define F1C 256
#define F2C 256
#define C0 259
#define H2 256
#define C2IN 512
#define NTILES 2048

// ---------------- scratch (__device__ globals) ----------------
__device__ float g_y0[(size_t)BB * MM * 128];                      // s0 * (W0_feat @ feature2)
__device__ __half g_midh[(size_t)BB * H2 * NN];                    // mlp1 output (fp16)
__device__ int   g_idx[BB * NN * KK];
__device__ __align__(16) uint16_t g_w1h[128 * 128];
__device__ __align__(16) uint16_t g_w2h[256 * 128];
__device__ __align__(16) uint16_t g_w20h[256 * 512];

__device__ __forceinline__ uint16_t f2h(float x) {
    return __half_as_ushort(__float2half_rn(x));
}
__device__ __forceinline__ uint32_t smem_u32(const void* p) {
    uint32_t a;
    asm("{ .reg .u64 t; cvta.to.shared.u64 t, %1; cvt.u32.u64 %0, t; }" : "=r"(a) : "l"(p));
    return a;
}
__device__ __forceinline__ uint32_t packh2(float lo, float hi) {
    return (uint32_t)f2h(lo) | ((uint32_t)f2h(hi) << 16);
}

// ---------------- mma.sync / ldmatrix / cp.async primitives ----------------
__device__ __forceinline__ void ldsm4(uint32_t r[4], uint32_t addr) {
    asm volatile("ldmatrix.sync.aligned.m8n8.x4.shared.b16 {%0,%1,%2,%3}, [%4];"
                 : "=r"(r[0]), "=r"(r[1]), "=r"(r[2]), "=r"(r[3]) : "r"(addr));
}
__device__ __forceinline__ void ldsm4t(uint32_t r[4], uint32_t addr) {
    asm volatile("ldmatrix.sync.aligned.m8n8.x4.trans.shared.b16 {%0,%1,%2,%3}, [%4];"
                 : "=r"(r[0]), "=r"(r[1]), "=r"(r[2]), "=r"(r[3]) : "r"(addr));
}
__device__ __forceinline__ void mma16816(float c[4], const uint32_t a[4], const uint32_t* b) {
    asm volatile("mma.sync.aligned.m16n8k16.row.col.f32.f16.f16.f32 "
                 "{%0,%1,%2,%3}, {%4,%5,%6,%7}, {%8,%9}, {%0,%1,%2,%3};"
                 : "+f"(c[0]), "+f"(c[1]), "+f"(c[2]), "+f"(c[3])
                 : "r"(a[0]), "r"(a[1]), "r"(a[2]), "r"(a[3]), "r"(b[0]), "r"(b[1]));
}
#define CP16(dst, src) asm volatile("cp.async.cg.shared.global [%0], [%1], 16;" :: "r"(dst), "l"(src))
#define CP_COMMIT()    asm volatile("cp.async.commit_group;")
#define CP_WAIT(n)     asm volatile("cp.async.wait_group %0;" :: "n"(n))

// ---------------------------------------------------------------------------
// prep: weights -> fp16 with BN scale folded in (W' = diag(s) W)
// ---------------------------------------------------------------------------
__global__ void prep_kernel(const float* __restrict__ W1, const float* __restrict__ S1,
                            const float* __restrict__ W2, const float* __restrict__ S2,
                            const float* __restrict__ W20, const float* __restrict__ S20) {
    int t = blockIdx.x * blockDim.x + threadIdx.x;
    if (t < 16384) {
        g_w1h[t] = f2h(W1[t] * __ldg(&S1[t >> 7]));
    } else if (t < 49152) {
        int i = t - 16384;
        g_w2h[i] = f2h(W2[i] * __ldg(&S2[i >> 7]));
    } else if (t < 180224) {
        int i = t - 49152;
        g_w20h[i] = f2h(W20[i] * __ldg(&S20[i >> 9]));
    }
}

// ---------------------------------------------------------------------------
// y0: g_y0[b][m][r] = S0[r] * sum_c W0[r][c] * feature2[b][c][m]   (fp32)
// ---------------------------------------------------------------------------
__global__ __launch_bounds__(128) void y0_kernel(const float* __restrict__ W0,
                                                 const float* __restrict__ S0,
                                                 const float* __restrict__ f2) {
    __shared__ float tile[256][33];
    const int b = blockIdx.y, m0 = blockIdx.x * 32, t = threadIdx.x;
    for (int i = t; i < 256 * 32; i += 128) {
        int c = i >> 5, j = i & 31;
        tile[c][j] = f2[((size_t)b * F2C + c) * MM + m0 + j];
    }
    __syncthreads();
    const int r = t;
    float acc[32];
#pragma unroll
    for (int j = 0; j < 32; j++) acc[j] = 0.0f;
    const float* wrow = W0 + (size_t)r * C0;
#pragma unroll 4
    for (int c = 0; c < 256; c++) {
        float w = __ldg(&wrow[c]);
#pragma unroll
        for (int j = 0; j < 32; j++) acc[j] = fmaf(w, tile[c][j], acc[j]);
    }
    float s0 = __ldg(&S0[r]);
    for (int j = 0; j < 32; j++)
        g_y0[((size_t)b * MM + m0 + j) * 128 + r] = acc[j] * s0;
}

// ---------------------------------------------------------------------------
// KNN: single full scan (2048 pts in smem), packed f32x2 FMA, top-8 -> g_idx.
// Strict < insertion keeps first occurrence on ties (matches top_k).
// ---------------------------------------------------------------------------
__global__ __launch_bounds__(128) void knn_scan(const float* __restrict__ pos1,
                                                const float* __restrict__ pos2) {
    __shared__ __align__(16) float sXY[MM * 2];
    __shared__ __align__(16) float sZW[MM * 2];
    const int b = blockIdx.z;
    const float* p2 = pos2 + (size_t)b * 3 * MM;
    for (int m = threadIdx.x; m < MM; m += 128) {
        float x = p2[m], y = p2[MM + m], z = p2[2 * MM + m];
        int pp = m >> 1, ln = m & 1;
        sXY[pp * 4 + ln] = x;     sXY[pp * 4 + 2 + ln] = y;
        sZW[pp * 4 + ln] = z;     sZW[pp * 4 + 2 + ln] = x * x + y * y + z * z;
    }
    __syncthreads();

    const int n = blockIdx.x * 128 + threadIdx.x;
    const float* p1 = pos1 + (size_t)b * 3 * NN;
    const float px = p1[n], py = p1[NN + n], pz = p1[2 * NN + n];
    const float n1 = px * px + py * py + pz * pz;
    const float mx2 = -2.0f * px, my2 = -2.0f * py, mz2 = -2.0f * pz;
    uint64_t QX, QY, QZ, NP;
    asm("mov.b64 %0, {%1, %2};" : "=l"(QX) : "f"(mx2), "f"(mx2));
    asm("mov.b64 %0, {%1, %2};" : "=l"(QY) : "f"(my2), "f"(my2));
    asm("mov.b64 %0, {%1, %2};" : "=l"(QZ) : "f"(mz2), "f"(mz2));
    asm("mov.b64 %0, {%1, %2};" : "=l"(NP) : "f"(n1), "f"(n1));

    float bestd[KK]; int besti[KK];
#pragma unroll
    for (int i = 0; i < KK; i++) { bestd[i] = 1e30f; besti[i] = 0; }
    float worst = 1e30f; int wslot = 0;

    auto ins = [&](float dv, int iv) {
        if (dv < worst) {
            bestd[wslot] = dv; besti[wslot] = iv;
            worst = bestd[0]; wslot = 0;
#pragma unroll
            for (int i = 1; i < KK; i++)
                if (bestd[i] > worst) { worst = bestd[i]; wslot = i; }
        }
    };

    uint32_t aXY = smem_u32(sXY), aZW = smem_u32(sZW);
    for (int g = 0; g < MM / 4; g++) {
        uint64_t X0, Y0, X1, Y1, Z0, W0, Z1, W1, t0, t1;
        asm("ld.shared.v2.u64 {%0,%1}, [%2];"    : "=l"(X0), "=l"(Y0) : "r"(aXY));
        asm("ld.shared.v2.u64 {%0,%1}, [%2+16];" : "=l"(X1), "=l"(Y1) : "r"(aXY));
        asm("ld.shared.v2.u64 {%0,%1}, [%2];"    : "=l"(Z0), "=l"(W0) : "r"(aZW));
        asm("ld.shared.v2.u64 {%0,%1}, [%2+16];" : "=l"(Z1), "=l"(W1) : "r"(aZW));
        aXY += 32; aZW += 32;
        asm("add.rn.f32x2 %0, %1, %2;"     : "=l"(t0) : "l"(W0), "l"(NP));
        asm("fma.rn.f32x2 %0, %1, %2, %3;" : "=l"(t0) : "l"(QZ), "l"(Z0), "l"(t0));
        asm("fma.rn.f32x2 %0, %1, %2, %3;" : "=l"(t0) : "l"(QY), "l"(Y0), "l"(t0));
        asm("fma.rn.f32x2 %0, %1, %2, %3;" : "=l"(t0) : "l"(QX), "l"(X0), "l"(t0));
        asm("add.rn.f32x2 %0, %1, %2;"     : "=l"(t1) : "l"(W1), "l"(NP));
        asm("fma.rn.f32x2 %0, %1, %2, %3;" : "=l"(t1) : "l"(QZ), "l"(Z1), "l"(t1));
        asm("fma.rn.f32x2 %0, %1, %2, %3;" : "=l"(t1) : "l"(QY), "l"(Y1), "l"(t1));
        asm("fma.rn.f32x2 %0, %1, %2, %3;" : "=l"(t1) : "l"(QX), "l"(X1), "l"(t1));
        float d0, d1, d2, d3;
        asm("mov.b64 {%0,%1}, %2;" : "=f"(d0), "=f"(d1) : "l"(t0));
        asm("mov.b64 {%0,%1}, %2;" : "=f"(d2), "=f"(d3) : "l"(t1));
        float mn = fminf(fminf(d0, d1), fminf(d2, d3));
        if (mn < worst) {
            int ib = g * 4;
            ins(d0, ib); ins(d1, ib + 1); ins(d2, ib + 2); ins(d3, ib + 3);
        }
    }
    int* out = g_idx + ((size_t)b * NN + n) * KK;
#pragma unroll
    for (int i = 0; i < KK; i++) out[i] = besti[i];
}

// ---------------------------------------------------------------------------
// mlp1 PERSISTENT: 1 CTA/SM; all three weight matrices resident in smem.
// Each block loops over tiles (16 points x 8 nbrs = 128 cols each).
// ---------------------------------------------------------------------------
#define LD1 136
#define X1OFF 0
#define WS1 34816
#define WS2 69632
#define WS3 104448
#define STGOFF 139264                  // 8192 B stage
#define PRMOFF 147456                  // sidx 512 | sw0pos 1536 | sB0 512 | sB1 512
#define DSMEM1 150528

__device__ __forceinline__ void cpa_w(uint32_t wdst, const uint16_t* gh, int t) {
#pragma unroll
    for (int k = 0; k < 8; k++) {
        int i = t + k * 256;
        CP16(wdst + (uint32_t)(((i >> 4) * 17 + (i & 15)) * 16), (const char*)gh + i * 16);
    }
}

// warp computes rows [mw*32, +32), cols [nw*64, +64); accum c[2][8][4]
__device__ __forceinline__ void gemm_ms(uint32_t xu, uint32_t wu, int mw, int nw,
                                        int lid, float c[2][8][4]) {
#pragma unroll
    for (int mi = 0; mi < 2; mi++)
#pragma unroll
        for (int nt = 0; nt < 8; nt++)
#pragma unroll
            for (int q = 0; q < 4; q++) c[mi][nt][q] = 0.0f;

    uint32_t aA0 = wu + (uint32_t)(((mw * 32 + (lid & 15)) * LD1 + (lid >> 4) * 8) * 2);
    uint32_t aA1 = aA0 + 16 * LD1 * 2;
    uint32_t aB  = xu + (uint32_t)(((lid & 15) * LD1 + nw * 64 + (lid >> 4) * 8) * 2);

#pragma unroll
    for (int kt = 0; kt < 8; kt++) {
        uint32_t A0[4], A1[4];
        ldsm4(A0, aA0 + kt * 32);
        ldsm4(A1, aA1 + kt * 32);
#pragma unroll
        for (int ng = 0; ng < 4; ng++) {
            uint32_t Bv[4];
            ldsm4t(Bv, aB + kt * 16 * LD1 * 2 + ng * 32);
            mma16816(c[0][2 * ng],     A0, Bv);
            mma16816(c[0][2 * ng + 1], A0, Bv + 2);
            mma16816(c[1][2 * ng],     A1, Bv);
            mma16816(c[1][2 * ng + 1], A1, Bv + 2);
        }
    }
}

__global__ __launch_bounds__(256, 1) void mlp1_mma(
    const float* __restrict__ pos1, const float* __restrict__ pos2,
    const float* __restrict__ W0full, const float* __restrict__ S0,
    const float* __restrict__ B0, const float* __restrict__ B1,
    const float* __restrict__ B2) {
    extern __shared__ __align__(32) char smp[];

    const int t = threadIdx.x, wid = t >> 5, lid = t & 31;
    const int mw = wid & 3, nw = wid >> 2;

    const uint32_t xu  = smem_u32(smp + X1OFF);
    const uint32_t wu1 = smem_u32(smp + WS1);
    const uint32_t wu2 = smem_u32(smp + WS2);
    const uint32_t wu3 = smem_u32(smp + WS3);
    uint16_t* stage  = (uint16_t*)(smp + STGOFF);
    int*   sidx   = (int*)(smp + PRMOFF);
    float* sw0pos = (float*)(smp + PRMOFF + 512);
    float* sB0    = (float*)(smp + PRMOFF + 2048);
    float* sB1    = (float*)(smp + PRMOFF + 2560);

    // load ALL weights once (async; waited before first gemm)
    cpa_w(wu1, g_w1h, t);
    cpa_w(wu2, g_w2h, t);
    cpa_w(wu3, g_w2h + 16384, t);
    CP_COMMIT();

    for (int i = t; i < 384; i += 256) {
        int d = i >> 7, r = i & 127;
        sw0pos[i] = W0full[(size_t)r * C0 + 256 + d] * __ldg(&S0[r]);
    }
    if (t < 128) { sB0[t] = B0[t]; sB1[t] = B1[t]; }

    float c[2][8][4];

    for (int tile = blockIdx.x; tile < NTILES; tile += gridDim.x) {
        const int b = tile >> 9, n0 = (tile & 511) * 16;

        if (t < 128) sidx[t] = g_idx[((size_t)b * NN + n0) * KK + t];
        __syncthreads();                              // sidx (+params, stage reuse) visible

        // ---- epilogue 0: gather y0 + pos correction, +b, ReLU -> X0 [k][n] ----
        {
            int c2 = t & 63, qh = t >> 6;
            int ca = 2 * c2;
            int ma = sidx[ca], mb2 = sidx[ca + 1];
            int n = n0 + (c2 >> 2);
            float pa0 = pos2[((size_t)b * 3 + 0) * MM + ma]  - pos1[((size_t)b * 3 + 0) * NN + n];
            float pa1 = pos2[((size_t)b * 3 + 1) * MM + ma]  - pos1[((size_t)b * 3 + 1) * NN + n];
            float pa2 = pos2[((size_t)b * 3 + 2) * MM + ma]  - pos1[((size_t)b * 3 + 2) * NN + n];
            float pb0 = pos2[((size_t)b * 3 + 0) * MM + mb2] - pos1[((size_t)b * 3 + 0) * NN + n];
            float pb1 = pos2[((size_t)b * 3 + 1) * MM + mb2] - pos1[((size_t)b * 3 + 1) * NN + n];
            float pb2 = pos2[((size_t)b * 3 + 2) * MM + mb2] - pos1[((size_t)b * 3 + 2) * NN + n];
            const float4* ya = (const float4*)(g_y0 + ((size_t)b * MM + ma)  * 128 + 32 * qh);
            const float4* yb = (const float4*)(g_y0 + ((size_t)b * MM + mb2) * 128 + 32 * qh);
            uint32_t* X32 = (uint32_t*)(smp + X1OFF);
#pragma unroll
            for (int i = 0; i < 8; i++) {
                float4 va = ya[i], vb = yb[i];
                float aa[4] = {va.x, va.y, va.z, va.w};
                float bb[4] = {vb.x, vb.y, vb.z, vb.w};
#pragma unroll
                for (int j = 0; j < 4; j++) {
                    int r = 32 * qh + i * 4 + j;
                    float w0 = sw0pos[r], w1 = sw0pos[128 + r], w2 = sw0pos[256 + r];
                    float fa = fmaxf(aa[j] + pa0 * w0 + pa1 * w1 + pa2 * w2 + sB0[r], 0.0f);
                    float fb = fmaxf(bb[j] + pb0 * w0 + pb1 * w1 + pb2 * w2 + sB0[r], 0.0f);
                    X32[r * (LD1 / 2) + c2] = packh2(fa, fb);
                }
            }
        }
        CP_WAIT(0);                                   // weights resident (no-op after tile 0)
        __syncthreads();

        // ---- layer 1: pack epilogue in regs BEFORE barrier ----
        gemm_ms(xu, wu1, mw, nw, lid, c);
        uint32_t pk[2][8][2];
#pragma unroll
        for (int mi = 0; mi < 2; mi++) {
            int r0 = mw * 32 + mi * 16 + (lid >> 2), r1 = r0 + 8;
            float b0 = sB1[r0], b1 = sB1[r1];
#pragma unroll
            for (int nt = 0; nt < 8; nt++) {
                pk[mi][nt][0] = packh2(fmaxf(c[mi][nt][0] + b0, 0.0f),
                                       fmaxf(c[mi][nt][1] + b0, 0.0f));
                pk[mi][nt][1] = packh2(fmaxf(c[mi][nt][2] + b1, 0.0f),
                                       fmaxf(c[mi][nt][3] + b1, 0.0f));
            }
        }
        __syncthreads();                              // all X0 reads complete
        {
            uint32_t* X32 = (uint32_t*)(smp + X1OFF);
#pragma unroll
            for (int mi = 0; mi < 2; mi++) {
                int r0 = mw * 32 + mi * 16 + (lid >> 2), r1 = r0 + 8;
#pragma unroll
                for (int nt = 0; nt < 8; nt++) {
                    int col = nw * 64 + nt * 8 + (lid & 3) * 2;
                    X32[(r0 * LD1 + col) >> 1] = pk[mi][nt][0];
                    X32[(r1 * LD1 + col) >> 1] = pk[mi][nt][1];
                }
            }
        }
        __syncthreads();                              // X1 visible

        // ---- layer 2: both halves back-to-back (weights resident) ----
#pragma unroll 1
        for (int h = 0; h < 2; h++) {
            gemm_ms(xu, h ? wu3 : wu2, mw, nw, lid, c);
#pragma unroll
            for (int mi = 0; mi < 2; mi++) {
                int r0 = mw * 32 + mi * 16 + (lid >> 2);
                int o0 = h * 128 + r0, o1 = o0 + 8;
#pragma unroll
                for (int nt = 0; nt < 8; nt++) {
                    int p = nw * 8 + nt;
                    float m0 = fmaxf(c[mi][nt][0], c[mi][nt][1]);
                    float m1 = fmaxf(c[mi][nt][2], c[mi][nt][3]);
                    m0 = fmaxf(m0, __shfl_xor_sync(0xffffffffu, m0, 1));
                    m0 = fmaxf(m0, __shfl_xor_sync(0xffffffffu, m0, 2));
                    m1 = fmaxf(m1, __shfl_xor_sync(0xffffffffu, m1, 1));
                    m1 = fmaxf(m1, __shfl_xor_sync(0xffffffffu, m1, 2));
                    if ((lid & 3) == 0) {
                        stage[o0 * 16 + p] = f2h(fmaxf(m0 + __ldg(&B2[o0]), 0.0f));
                        stage[o1 * 16 + p] = f2h(fmaxf(m1 + __ldg(&B2[o1]), 0.0f));
                    }
                }
            }
        }
        __syncthreads();                              // stage complete; X reads done
        {
            const uint4* s = (const uint4*)(stage + t * 16);
            uint4* d = (uint4*)(&g_midh[((size_t)b * H2 + t) * NN + n0]);
            d[0] = s[0]; d[1] = s[1];
        }
        // loop-top __syncthreads orders stage reads before next tile's writes
    }
}

// ---------------------------------------------------------------------------
// mlp2 (wmma fp16): out = relu(W20' @ concat(g_midh, f1) + b), 512 -> 256.
// ---------------------------------------------------------------------------
#define LDX 136
#define OFF_X 0
#define OFF_W 34816
#define OFF_SCR 69632
#define DSMEM2 79872

typedef wmma::fragment<wmma::matrix_a, 16, 16, 16, __half, wmma::row_major> frag_a;
typedef wmma::fragment<wmma::matrix_b, 16, 16, 16, __half, wmma::row_major> frag_br;
typedef wmma::fragment<wmma::accumulator, 16, 16, 16, float> frag_c;

__global__ __launch_bounds__(256, 2) void mlp2_wmma(
    const float* __restrict__ f1,
    const float* __restrict__ Bi, float* __restrict__ out) {
    extern __shared__ __align__(32) char smp[];
    const int t = threadIdx.x, wid = t >> 5, lid = t & 31;
    const int mw = wid & 3, nw = wid >> 2;
    const int b = blockIdx.z, m0b = blockIdx.y * 128, n0 = blockIdx.x * 128;

    uint16_t* Xc = (uint16_t*)(smp + OFF_X);
    uint16_t* Wc = (uint16_t*)(smp + OFF_W);
    float* scr = (float*)(smp + OFF_SCR) + wid * 320;

    frag_c c[2][4];
#pragma unroll
    for (int mi = 0; mi < 2; mi++)
#pragma unroll
        for (int nt = 0; nt < 4; nt++) wmma::fill_fragment(c[mi][nt], 0.0f);

    for (int ch = 0; ch < C2IN; ch += 128) {
        {
            uint32_t wdst = smem_u32(Wc);
            for (int i = t; i < 2048; i += 256)
                CP16(wdst + (uint32_t)(((i >> 4) * 17 + (i & 15)) * 16),
                     (const char*)(g_w20h + (size_t)(m0b + (i >> 4)) * 512 + ch) + (i & 15) * 16);
        }
        {
            uint4* d = (uint4*)Xc;
            if (ch < 256) {
                uint32_t xdst = smem_u32(Xc);
                const char* src = (const char*)&g_midh[((size_t)b * H2 + ch) * NN + n0];
                for (int i = t; i < 2048; i += 256)
                    CP16(xdst + (uint32_t)(((i >> 4) * 17 + (i & 15)) * 16),
                         src + (size_t)(i >> 4) * NN * 2 + (i & 15) * 16);
            } else {
                const float* srcf = f1 + ((size_t)b * F1C + (ch - 256)) * NN + n0;
                for (int i = t; i < 2048; i += 256) {
                    int row = i >> 4, q = i & 15;
                    const float4* s4 = (const float4*)(srcf + (size_t)row * NN);
                    float4 a = s4[q * 2], c2 = s4[q * 2 + 1];
                    uint4 v;
                    v.x = packh2(a.x, a.y);  v.y = packh2(a.z, a.w);
                    v.z = packh2(c2.x, c2.y); v.w = packh2(c2.z, c2.w);
                    d[row * 17 + q] = v;
                }
            }
        }
        CP_COMMIT();
        CP_WAIT(0);
        __syncthreads();
        const __half* Wp = (const __half*)Wc;
        const __half* Xp = (const __half*)Xc;
        for (int k0 = 0; k0 < 128; k0 += 16) {
            frag_a a0, a1;
            wmma::load_matrix_sync(a0, Wp + (mw * 32) * LDX + k0, LDX);
            wmma::load_matrix_sync(a1, Wp + (mw * 32 + 16) * LDX + k0, LDX);
#pragma unroll
            for (int nt = 0; nt < 4; nt++) {
                frag_br bb;
                wmma::load_matrix_sync(bb, Xp + k0 * LDX + (nw * 64 + nt * 16), LDX);
                wmma::mma_sync(c[0][nt], a0, bb, c[0][nt]);
                wmma::mma_sync(c[1][nt], a1, bb, c[1][nt]);
            }
        }
        __syncthreads();
    }

#pragma unroll
    for (int mi = 0; mi < 2; mi++)
#pragma unroll
        for (int nt = 0; nt < 4; nt++) {
            wmma::store_matrix_sync(scr, c[mi][nt], 20, wmma::mem_row_major);
            __syncwarp();
            int colin = lid & 15, rh = lid >> 4;
            int o = m0b + mw * 32 + mi * 16;
            int colg = n0 + nw * 64 + nt * 16 + colin;
#pragma unroll
            for (int j = 0; j < 8; j++) {
                int r = rh * 8 + j;
                float y = fmaxf(scr[r * 20 + colin] + __ldg(&Bi[o + r]), 0.0f);
                out[((size_t)b * H2 + o + r) * NN + colg] = y;
            }
            __syncwarp();
        }
}

// ---------------------------------------------------------------------------
extern "C" void kernel_launch(void* const* d_in, const int* in_sizes, int n_in,
                              void* d_out, int out_size) {
    const float* pos1     = (const float*)d_in[0];
    const float* pos2     = (const float*)d_in[1];
    const float* feature1 = (const float*)d_in[2];
    const float* feature2 = (const float*)d_in[3];
    const float* w1_0 = (const float*)d_in[4];
    const float* s1_0 = (const float*)d_in[5];
    const float* b1_0 = (const float*)d_in[6];
    const float* w1_1 = (const float*)d_in[7];
    const float* s1_1 = (const float*)d_in[8];
    const float* b1_1 = (const float*)d_in[9];
    const float* w1_2 = (const float*)d_in[10];
    const float* s1_2 = (const float*)d_in[11];
    const float* b1_2 = (const float*)d_in[12];
    const float* w2_0 = (const float*)d_in[13];
    const float* s2_0 = (const float*)d_in[14];
    const float* b2_0 = (const float*)d_in[15];
    float* out = (float*)d_out;

    static int nsm = 0;
    static cudaStream_t s2;
    static cudaEvent_t ev0, ev1;
    static int init_done = 0;
    if (!init_done) {
        cudaFuncSetAttribute(mlp1_mma, cudaFuncAttributeMaxDynamicSharedMemorySize, DSMEM1);
        cudaFuncSetAttribute(mlp2_wmma, cudaFuncAttributeMaxDynamicSharedMemorySize, DSMEM2);
        cudaDeviceGetAttribute(&nsm, cudaDevAttrMultiProcessorCount, 0);
        cudaStreamCreateWithFlags(&s2, cudaStreamNonBlocking);
        cudaEventCreateWithFlags(&ev0, cudaEventDisableTiming);
        cudaEventCreateWithFlags(&ev1, cudaEventDisableTiming);
        init_done = 1;
    }

    // fork: knn on side stream, prep+y0 on main stream
    cudaEventRecord(ev0, 0);
    cudaStreamWaitEvent(s2, ev0, 0);
    knn_scan<<<dim3(NN / 128, 1, BB), 128, 0, s2>>>(pos1, pos2);
    cudaEventRecord(ev1, s2);

    prep_kernel<<<704, 256>>>(w1_1, s1_1, w1_2, s1_2, w2_0, s2_0);
    y0_kernel<<<dim3(MM / 32, BB), 128>>>(w1_0, s1_0, feature2);

    cudaStreamWaitEvent(0, ev1, 0);                   // join

    mlp1_mma<<<nsm, 256, DSMEM1>>>(pos1, pos2, w1_0, s1_0, b1_0, b1_1, b1_2);
    mlp2_wmma<<<dim3(NN / 128, 2, BB), 256, DSMEM2>>>(feature1, b2_0, out);
}